// round 3
// baseline (speedup 1.0000x reference)
#include <cuda_runtime.h>
#include <math.h>

#define UU 4096
#define II 16384
#define DD 64
#define NNODES (UU + II)   // 20480
#define NEI 524288
#define NES 65536

// ---------------- device scratch (no allocation allowed) ----------------
__device__ float g_h0[NNODES * DD];
__device__ float g_h1[NNODES * DD];
__device__ float g_acc[UU * DD];
__device__ float g_ue[UU * DD];

__device__ int   g_cnt_i[NNODES + 1];
__device__ int   g_rptr_i[NNODES + 1];
__device__ int   g_cur_i[NNODES + 1];
__device__ int   g_colp_i[NEI];
__device__ float g_valp_i[NEI];

__device__ int   g_cnt_s[UU + 1];
__device__ int   g_rptr_s[UU + 1];
__device__ int   g_cur_s[UU + 1];
__device__ int   g_colp_s[NES];
__device__ float g_valp_s[NES];

__device__ float g_Ka[DD * DD];
__device__ float g_Kb[DD * DD];
__device__ float g_Pa[UU * DD];
__device__ float g_Pb[UU * DD];
__device__ float g_ew[NES];

// ---------------- generic CSR machinery ----------------
__global__ void k_zero_counts() {
    int t = blockIdx.x * blockDim.x + threadIdx.x;
    if (t <= NNODES) g_cnt_i[t] = 0;
    if (t <= UU)     g_cnt_s[t] = 0;
}

__global__ void k_hist(const int* __restrict__ rows, int ne, int* cnt) {
    for (int e = blockIdx.x * blockDim.x + threadIdx.x; e < ne;
         e += gridDim.x * blockDim.x)
        atomicAdd(&cnt[rows[e]], 1);
}

// exclusive scan over n entries, single block of 1024 threads
__global__ void k_scan(const int* __restrict__ cnt, int* rptr, int* cur, int n) {
    __shared__ int sh[1024];
    __shared__ int off;
    int t = threadIdx.x;
    if (t == 0) off = 0;
    __syncthreads();
    for (int base = 0; base < n; base += 1024) {
        int i = base + t;
        int v = (i < n) ? cnt[i] : 0;
        sh[t] = v;
        __syncthreads();
        int x = v;
        for (int dlt = 1; dlt < 1024; dlt <<= 1) {
            int y = (t >= dlt) ? sh[t - dlt] : 0;
            __syncthreads();
            x += y;
            sh[t] = x;
            __syncthreads();
        }
        int excl = off + x - v;
        if (i < n) { rptr[i] = excl; cur[i] = excl; }
        int blocktot = sh[1023];
        __syncthreads();
        if (t == 0) off += blocktot;
        __syncthreads();
    }
    if (t == 0) { rptr[n] = off; cur[n] = off; }
}

__global__ void k_scatter(const int* __restrict__ rows, const int* __restrict__ cols,
                          const float* __restrict__ vals, int ne,
                          int* cur, int* ocol, float* oval) {
    for (int e = blockIdx.x * blockDim.x + threadIdx.x; e < ne;
         e += gridDim.x * blockDim.x) {
        int r = rows[e];
        int p = atomicAdd(&cur[r], 1);
        ocol[p] = cols[e];
        oval[p] = vals[e];
    }
}

// ---------------- LightGCN ----------------
__global__ void k_init_h(const float* __restrict__ ue_in, const float* __restrict__ ie_in) {
    int t = blockIdx.x * blockDim.x + threadIdx.x;
    if (t < UU * DD) {
        float v = ue_in[t];
        g_h0[t] = v;
        g_acc[t] = v;
    } else if (t < NNODES * DD) {
        g_h0[t] = ie_in[t - UU * DD];
    }
}

// one row per 64 threads; 2 rows per block
__global__ void k_spmm(int srcIs0) {
    const float* __restrict__ src = srcIs0 ? g_h0 : g_h1;
    float* __restrict__ dst = srcIs0 ? g_h1 : g_h0;
    int row = blockIdx.x * 2 + threadIdx.y;
    int d = threadIdx.x;
    int b = g_rptr_i[row], e = g_rptr_i[row + 1];
    float a = 0.f;
    int k = b;
    for (; k + 1 < e; k += 2) {
        int c0 = g_colp_i[k];
        int c1 = g_colp_i[k + 1];
        float v0 = g_valp_i[k];
        float v1 = g_valp_i[k + 1];
        float x0 = src[c0 * DD + d];
        float x1 = src[c1 * DD + d];
        a += v0 * x0;
        a += v1 * x1;
    }
    if (k < e) {
        int c = g_colp_i[k];
        a += g_valp_i[k] * src[c * DD + d];
    }
    dst[row * DD + d] = a;
    if (row < UU) g_acc[row * DD + d] += a;
}

__global__ void k_fin_ue() {
    int t = blockIdx.x * blockDim.x + threadIdx.x;
    if (t < UU * DD) g_ue[t] = g_acc[t] * 0.25f;
}

// ---------------- social edge MLP precompute ----------------
// Ka = Wa @ w1[:64,:]  ; Kb = Wb @ w1[64:,:]
__global__ void k_kab(const float* __restrict__ Wa, const float* __restrict__ Wb,
                      const float* __restrict__ w1) {
    int t = blockIdx.x * blockDim.x + threadIdx.x;   // 8192
    int which = t >> 12;
    int idx = t & 4095;
    int k = idx >> 6, j = idx & 63;
    const float* W = which ? Wb : Wa;
    const float* w1p = which ? (w1 + 64 * 64) : w1;
    float s = 0.f;
#pragma unroll 8
    for (int m = 0; m < 64; m++) s += W[k * 64 + m] * w1p[m * 64 + j];
    if (which) g_Kb[idx] = s; else g_Ka[idx] = s;
}

// Pa = U @ Ka ; Pb = U @ Kb + b1
__global__ void k_pab(const float* __restrict__ ue_in, const float* __restrict__ b1) {
    __shared__ float sKa[64 * 64];
    __shared__ float sKb[64 * 64];
    int t = threadIdx.y * 64 + threadIdx.x;
    for (int q = t; q < 4096; q += 256) { sKa[q] = g_Ka[q]; sKb[q] = g_Kb[q]; }
    __syncthreads();
    int i = blockIdx.x * 4 + threadIdx.y;
    int j = threadIdx.x;
    float a = 0.f, bb = 0.f;
#pragma unroll 8
    for (int k = 0; k < 64; k++) {
        float u = ue_in[i * 64 + k];
        a += u * sKa[k * 64 + j];
        bb += u * sKb[k * 64 + j];
    }
    g_Pa[i * 64 + j] = a;
    g_Pb[i * 64 + j] = bb + b1[j];
}

// edge_w[e] = sigmoid( relu(Pa[col]+Pb[row]) . w2 + b2 )  -- one warp per edge
__global__ void k_edge(const int* __restrict__ srows, const int* __restrict__ scols,
                       const float* __restrict__ w2, const float* __restrict__ b2) {
    int warp = (blockIdx.x * blockDim.x + threadIdx.x) >> 5;
    int lane = threadIdx.x & 31;
    if (warp >= NES) return;
    int r = srows[warp], c = scols[warp];
    float h0 = g_Pa[c * 64 + lane] + g_Pb[r * 64 + lane];
    float h1 = g_Pa[c * 64 + 32 + lane] + g_Pb[r * 64 + 32 + lane];
    h0 = fmaxf(h0, 0.f);
    h1 = fmaxf(h1, 0.f);
    float p = h0 * w2[lane] + h1 * w2[lane + 32];
#pragma unroll
    for (int o = 16; o; o >>= 1) p += __shfl_down_sync(0xffffffffu, p, o);
    if (lane == 0) g_ew[warp] = 1.f / (1.f + expf(-(p + b2[0])));
}

// ---------------- social propagation (sparse masked softmax) ----------------
// Per block = one user row i. Build merged dense row of A and of A2=A@A in
// shared, softmax over structural nonzeros, accumulate semb1/semb2, emit
// out[i] = (4/3)*ue[i] + (semb1+semb2)/3.
__global__ void k_social(float* __restrict__ out) {
    __shared__ float rA[UU];
    __shared__ float rA2[UU];
    __shared__ float red[256];
    __shared__ float sg1[4][64];
    __shared__ float sg2[4][64];

    int i = blockIdx.x;
    int t = threadIdx.x;  // 256

    // zero rows (float4)
    float4* rA4 = (float4*)rA;
    float4* rB4 = (float4*)rA2;
    float4 z4 = make_float4(0.f, 0.f, 0.f, 0.f);
    for (int q = t; q < UU / 4; q += 256) { rA4[q] = z4; rB4[q] = z4; }
    __syncthreads();

    int b = g_rptr_s[i], e = g_rptr_s[i + 1];
    // depth-1: merged A row (duplicates summed)
    for (int k = b + t; k < e; k += 256)
        atomicAdd(&rA[g_colp_s[k]], g_valp_s[k]);
    // depth-2: A2[i,:] += w_ik * A[k,:]  (via edge lists; duplicates additive)
    for (int k = b + t; k < e; k += 256) {
        int kk = g_colp_s[k];
        float w = g_valp_s[k];
        int b2i = g_rptr_s[kk], e2i = g_rptr_s[kk + 1];
        for (int m = b2i; m < e2i; m++)
            atomicAdd(&rA2[g_colp_s[m]], w * g_valp_s[m]);
    }
    __syncthreads();

    // in-place masked softmax on both rows
    for (int which = 0; which < 2; which++) {
        float* row = which ? rA2 : rA;
        float mx = -1e30f;
        for (int j = t; j < UU; j += 256) {
            float a = row[j];
            if (a > 0.f) mx = fmaxf(mx, a);
        }
        red[t] = mx; __syncthreads();
        for (int s = 128; s; s >>= 1) {
            if (t < s) red[t] = fmaxf(red[t], red[t + s]);
            __syncthreads();
        }
        mx = red[0]; __syncthreads();

        float sum = 0.f;
        for (int j = t; j < UU; j += 256) {
            float a = row[j];
            if (a > 0.f) sum += expf(a - mx);
        }
        red[t] = sum; __syncthreads();
        for (int s = 128; s; s >>= 1) {
            if (t < s) red[t] += red[t + s];
            __syncthreads();
        }
        sum = red[0]; __syncthreads();

        float inv = (sum > 0.f) ? 1.f / sum : 0.f;
        for (int j = t; j < UU; j += 256) {
            float a = row[j];
            row[j] = (a > 0.f) ? expf(a - mx) * inv : 0.f;
        }
        __syncthreads();
    }

    // weighted accumulation of user_e; 4 groups x 64 d-lanes
    int g = t >> 6;
    int d = t & 63;
    float o1 = 0.f, o2 = 0.f;
    for (int j = g; j < UU; j += 4) {
        float p1 = rA[j];
        float p2 = rA2[j];
        if (p1 > 0.f || p2 > 0.f) {
            float u = g_ue[j * 64 + d];
            o1 += p1 * u;
            o2 += p2 * u;
        }
    }
    sg1[g][d] = o1;
    sg2[g][d] = o2;
    __syncthreads();
    if (g == 0) {
        float tot = sg1[0][d] + sg1[1][d] + sg1[2][d] + sg1[3][d]
                  + sg2[0][d] + sg2[1][d] + sg2[2][d] + sg2[3][d];
        out[i * 64 + d] = (4.f / 3.f) * g_ue[i * 64 + d] + tot * (1.f / 3.f);
    }
}

// ---------------- launch ----------------
extern "C" void kernel_launch(void* const* d_in, const int* in_sizes, int n_in,
                              void* d_out, int out_size) {
    const float* ue_in = (const float*)d_in[0];
    const float* ie_in = (const float*)d_in[1];
    const float* ivals = (const float*)d_in[2];
    const float* Wa    = (const float*)d_in[3];
    const float* Wb    = (const float*)d_in[4];
    const float* w1    = (const float*)d_in[5];
    const float* b1    = (const float*)d_in[6];
    const float* w2    = (const float*)d_in[7];
    const float* b2    = (const float*)d_in[8];
    const int* irows   = (const int*)d_in[9];
    const int* icols   = (const int*)d_in[10];
    const int* srows   = (const int*)d_in[11];
    const int* scols   = (const int*)d_in[12];
    float* out = (float*)d_out;

    int *p_cnt_i, *p_rptr_i, *p_cur_i, *p_col_i;
    int *p_cnt_s, *p_rptr_s, *p_cur_s, *p_col_s;
    float *p_val_i, *p_val_s, *p_ew;
    cudaGetSymbolAddress((void**)&p_cnt_i,  g_cnt_i);
    cudaGetSymbolAddress((void**)&p_rptr_i, g_rptr_i);
    cudaGetSymbolAddress((void**)&p_cur_i,  g_cur_i);
    cudaGetSymbolAddress((void**)&p_col_i,  g_colp_i);
    cudaGetSymbolAddress((void**)&p_val_i,  g_valp_i);
    cudaGetSymbolAddress((void**)&p_cnt_s,  g_cnt_s);
    cudaGetSymbolAddress((void**)&p_rptr_s, g_rptr_s);
    cudaGetSymbolAddress((void**)&p_cur_s,  g_cur_s);
    cudaGetSymbolAddress((void**)&p_col_s,  g_colp_s);
    cudaGetSymbolAddress((void**)&p_val_s,  g_valp_s);
    cudaGetSymbolAddress((void**)&p_ew,     g_ew);

    // interaction-graph CSR
    k_zero_counts<<<(NNODES + 256) / 256, 256>>>();
    k_hist<<<1024, 256>>>(irows, NEI, p_cnt_i);
    k_scan<<<1, 1024>>>(p_cnt_i, p_rptr_i, p_cur_i, NNODES);
    k_scatter<<<1024, 256>>>(irows, icols, ivals, NEI, p_cur_i, p_col_i, p_val_i);

    // LightGCN: 3 SpMM layers, mean over {h0..h3} of user rows
    k_init_h<<<(NNODES * DD + 255) / 256, 256>>>(ue_in, ie_in);
    k_spmm<<<NNODES / 2, dim3(64, 2)>>>(1);
    k_spmm<<<NNODES / 2, dim3(64, 2)>>>(0);
    k_spmm<<<NNODES / 2, dim3(64, 2)>>>(1);
    k_fin_ue<<<(UU * DD + 255) / 256, 256>>>();

    // social edge weights (fused MLP)
    k_kab<<<32, 256>>>(Wa, Wb, w1);
    k_pab<<<UU / 4, dim3(64, 4)>>>(ue_in, b1);
    k_edge<<<NES / 8, 256>>>(srows, scols, w2, b2);

    // social-graph CSR (weights = edge_w)
    k_hist<<<256, 256>>>(srows, NES, p_cnt_s);
    k_scan<<<1, 1024>>>(p_cnt_s, p_rptr_s, p_cur_s, UU);
    k_scatter<<<256, 256>>>(srows, scols, p_ew, NES, p_cur_s, p_col_s, p_val_s);

    // sparse masked-softmax propagation + final combine
    k_social<<<UU, 256>>>(out);
}

// round 4
// speedup vs baseline: 2.3895x; 2.3895x over previous
#include <cuda_runtime.h>
#include <math.h>

#define UU 4096
#define II 16384
#define DD 64
#define NNODES (UU + II)   // 20480
#define NEI 524288
#define NES 65536

// ---------------- device scratch (no allocation allowed) ----------------
__device__ float g_h0[NNODES * DD];
__device__ float g_h1[NNODES * DD];
__device__ float g_acc[UU * DD];
__device__ float g_ue[UU * DD];

__device__ int   g_cnt_i[NNODES + 1];
__device__ int   g_rptr_i[NNODES + 1];
__device__ int   g_cur_i[NNODES + 1];
__device__ int   g_colp_i[NEI];
__device__ float g_valp_i[NEI];

__device__ int   g_cnt_s[UU + 1];
__device__ int   g_rptr_s[UU + 1];
__device__ int   g_cur_s[UU + 1];
__device__ int   g_colp_s[NES];
__device__ float g_valp_s[NES];

__device__ float g_Ka[DD * DD];
__device__ float g_Kb[DD * DD];
__device__ float g_Pa[UU * DD];
__device__ float g_Pb[UU * DD];
__device__ float g_ew[NES];

// ---------------- generic CSR machinery ----------------
__global__ void k_zero_counts() {
    int t = blockIdx.x * blockDim.x + threadIdx.x;
    if (t <= NNODES) g_cnt_i[t] = 0;
    if (t <= UU)     g_cnt_s[t] = 0;
}

__global__ void k_hist(const int* __restrict__ rows, int ne, int* cnt) {
    for (int e = blockIdx.x * blockDim.x + threadIdx.x; e < ne;
         e += gridDim.x * blockDim.x)
        atomicAdd(&cnt[rows[e]], 1);
}

// exclusive scan over n entries, single block of 1024 threads, warp-shuffle based
__global__ void k_scan(const int* __restrict__ cnt, int* rptr, int* cur, int n) {
    __shared__ int wsum[32];
    __shared__ int soff;
    int t = threadIdx.x;
    int lane = t & 31, w = t >> 5;
    if (t == 0) soff = 0;
    __syncthreads();
    for (int base = 0; base < n; base += 1024) {
        int i = base + t;
        int v = (i < n) ? cnt[i] : 0;
        int x = v;
#pragma unroll
        for (int d = 1; d < 32; d <<= 1) {
            int y = __shfl_up_sync(0xffffffffu, x, d);
            if (lane >= d) x += y;
        }
        if (lane == 31) wsum[w] = x;
        __syncthreads();
        if (w == 0) {
            int s = wsum[lane];
            int xs = s;
#pragma unroll
            for (int d = 1; d < 32; d <<= 1) {
                int y = __shfl_up_sync(0xffffffffu, xs, d);
                if (lane >= d) xs += y;
            }
            wsum[lane] = xs - s;   // exclusive warp offset
        }
        __syncthreads();
        int excl = soff + wsum[w] + x - v;
        if (i < n) { rptr[i] = excl; cur[i] = excl; }
        __syncthreads();
        if (t == 1023) soff += wsum[31] + x;   // exclusive offset of last warp + its inclusive sum
        __syncthreads();
    }
    if (t == 0) { rptr[n] = soff; cur[n] = soff; }
}

__global__ void k_scatter(const int* __restrict__ rows, const int* __restrict__ cols,
                          const float* __restrict__ vals, int ne,
                          int* cur, int* ocol, float* oval) {
    for (int e = blockIdx.x * blockDim.x + threadIdx.x; e < ne;
         e += gridDim.x * blockDim.x) {
        int r = rows[e];
        int p = atomicAdd(&cur[r], 1);
        ocol[p] = cols[e];
        oval[p] = vals[e];
    }
}

// ---------------- LightGCN ----------------
__global__ void k_init_h(const float* __restrict__ ue_in, const float* __restrict__ ie_in) {
    int t = blockIdx.x * blockDim.x + threadIdx.x;
    if (t < UU * DD) {
        float v = ue_in[t];
        g_h0[t] = v;
        g_acc[t] = v;
    } else if (t < NNODES * DD) {
        g_h0[t] = ie_in[t - UU * DD];
    }
}

// one row per 64 threads; 4 rows per block; unroll 4 for MLP
__global__ void k_spmm(int srcIs0) {
    const float* __restrict__ src = srcIs0 ? g_h0 : g_h1;
    float* __restrict__ dst = srcIs0 ? g_h1 : g_h0;
    int row = blockIdx.x * 4 + threadIdx.y;
    int d = threadIdx.x;
    int b = g_rptr_i[row], e = g_rptr_i[row + 1];
    float a = 0.f;
    int k = b;
    for (; k + 3 < e; k += 4) {
        int   c0 = g_colp_i[k],     c1 = g_colp_i[k + 1];
        int   c2 = g_colp_i[k + 2], c3 = g_colp_i[k + 3];
        float v0 = g_valp_i[k],     v1 = g_valp_i[k + 1];
        float v2 = g_valp_i[k + 2], v3 = g_valp_i[k + 3];
        float x0 = src[c0 * DD + d];
        float x1 = src[c1 * DD + d];
        float x2 = src[c2 * DD + d];
        float x3 = src[c3 * DD + d];
        a += v0 * x0; a += v1 * x1; a += v2 * x2; a += v3 * x3;
    }
    for (; k < e; k++)
        a += g_valp_i[k] * src[g_colp_i[k] * DD + d];
    dst[row * DD + d] = a;
    if (row < UU) g_acc[row * DD + d] += a;
}

__global__ void k_fin_ue() {
    int t = blockIdx.x * blockDim.x + threadIdx.x;
    if (t < UU * DD) g_ue[t] = g_acc[t] * 0.25f;
}

// ---------------- social edge MLP precompute ----------------
__global__ void k_kab(const float* __restrict__ Wa, const float* __restrict__ Wb,
                      const float* __restrict__ w1) {
    int t = blockIdx.x * blockDim.x + threadIdx.x;   // 8192
    int which = t >> 12;
    int idx = t & 4095;
    int k = idx >> 6, j = idx & 63;
    const float* W = which ? Wb : Wa;
    const float* w1p = which ? (w1 + 64 * 64) : w1;
    float s = 0.f;
#pragma unroll 8
    for (int m = 0; m < 64; m++) s += W[k * 64 + m] * w1p[m * 64 + j];
    if (which) g_Kb[idx] = s; else g_Ka[idx] = s;
}

__global__ void k_pab(const float* __restrict__ ue_in, const float* __restrict__ b1) {
    __shared__ float sKa[64 * 64];
    __shared__ float sKb[64 * 64];
    int t = threadIdx.y * 64 + threadIdx.x;
    for (int q = t; q < 4096; q += 256) { sKa[q] = g_Ka[q]; sKb[q] = g_Kb[q]; }
    __syncthreads();
    int i = blockIdx.x * 4 + threadIdx.y;
    int j = threadIdx.x;
    float a = 0.f, bb = 0.f;
#pragma unroll 8
    for (int k = 0; k < 64; k++) {
        float u = ue_in[i * 64 + k];
        a += u * sKa[k * 64 + j];
        bb += u * sKb[k * 64 + j];
    }
    g_Pa[i * 64 + j] = a;
    g_Pb[i * 64 + j] = bb + b1[j];
}

__global__ void k_edge(const int* __restrict__ srows, const int* __restrict__ scols,
                       const float* __restrict__ w2, const float* __restrict__ b2) {
    int warp = (blockIdx.x * blockDim.x + threadIdx.x) >> 5;
    int lane = threadIdx.x & 31;
    if (warp >= NES) return;
    int r = srows[warp], c = scols[warp];
    float h0 = g_Pa[c * 64 + lane] + g_Pb[r * 64 + lane];
    float h1 = g_Pa[c * 64 + 32 + lane] + g_Pb[r * 64 + 32 + lane];
    h0 = fmaxf(h0, 0.f);
    h1 = fmaxf(h1, 0.f);
    float p = h0 * w2[lane] + h1 * w2[lane + 32];
#pragma unroll
    for (int o = 16; o; o >>= 1) p += __shfl_down_sync(0xffffffffu, p, o);
    if (lane == 0) g_ew[warp] = 1.f / (1.f + expf(-(p + b2[0])));
}

// ---------------- social propagation (sparse masked softmax) ----------------
// Per block = one user row i. Build merged dense rows of A and A2=A@A in
// shared, COMPACT the nonzero-column union into a 16-bit list, then do
// softmax reductions + weighted user_e gather over the list only.
__global__ void k_social(float* __restrict__ out) {
    __shared__ float rA[UU];             // 16 KB
    __shared__ float rA2[UU];            // 16 KB
    __shared__ unsigned short lst[UU];   // 8 KB
    __shared__ int nlst;
    __shared__ float red[256];
    __shared__ float red2[256];
    __shared__ float sg1[4][64];
    __shared__ float sg2[4][64];

    int i = blockIdx.x;
    int t = threadIdx.x;  // 256
    int lane = t & 31;

    // zero rows (float4)
    float4* rA4 = (float4*)rA;
    float4* rB4 = (float4*)rA2;
    float4 z4 = make_float4(0.f, 0.f, 0.f, 0.f);
    for (int q = t; q < UU / 4; q += 256) { rA4[q] = z4; rB4[q] = z4; }
    if (t == 0) nlst = 0;
    __syncthreads();

    int b = g_rptr_s[i], e = g_rptr_s[i + 1];
    // depth-1: merged A row (duplicates summed)
    for (int k = b + t; k < e; k += 256)
        atomicAdd(&rA[g_colp_s[k]], g_valp_s[k]);
    // depth-2: A2[i,:] += w_ik * A[k,:]  — 16 threads cooperate per neighbor k
    for (int k = b + (t >> 4); k < e; k += 16) {
        int kk = g_colp_s[k];
        float w = g_valp_s[k];
        int b2i = g_rptr_s[kk], e2i = g_rptr_s[kk + 1];
        for (int m = b2i + (t & 15); m < e2i; m += 16)
            atomicAdd(&rA2[g_colp_s[m]], w * g_valp_s[m]);
    }
    __syncthreads();

    // compact union of nonzero columns (warp-aggregated push)
    for (int j = t; j < UU; j += 256) {
        bool nz = (rA[j] > 0.f) || (rA2[j] > 0.f);
        unsigned mask = __ballot_sync(0xffffffffu, nz);
        if (nz) {
            int lead = __ffs(mask) - 1;
            int basep = 0;
            if (lane == lead) basep = atomicAdd(&nlst, __popc(mask));
            basep = __shfl_sync(mask, basep, lead);
            int off = __popc(mask & ((1u << lane) - 1u));
            lst[basep + off] = (unsigned short)j;
        }
    }
    __syncthreads();
    int L = nlst;

    // max over list (both rows)
    float m1 = -1e30f, m2 = -1e30f;
    for (int q = t; q < L; q += 256) {
        int j = lst[q];
        float a1 = rA[j], a2 = rA2[j];
        if (a1 > 0.f) m1 = fmaxf(m1, a1);
        if (a2 > 0.f) m2 = fmaxf(m2, a2);
    }
    red[t] = m1; red2[t] = m2; __syncthreads();
    for (int s = 128; s; s >>= 1) {
        if (t < s) {
            red[t] = fmaxf(red[t], red[t + s]);
            red2[t] = fmaxf(red2[t], red2[t + s]);
        }
        __syncthreads();
    }
    m1 = red[0]; m2 = red2[0];
    __syncthreads();

    // exp + sums; write exp back into rows (list entries are unique -> no races)
    float s1 = 0.f, s2 = 0.f;
    for (int q = t; q < L; q += 256) {
        int j = lst[q];
        float a1 = rA[j], a2 = rA2[j];
        float e1 = (a1 > 0.f) ? expf(a1 - m1) : 0.f;
        float e2 = (a2 > 0.f) ? expf(a2 - m2) : 0.f;
        rA[j] = e1; rA2[j] = e2;
        s1 += e1; s2 += e2;
    }
    red[t] = s1; red2[t] = s2; __syncthreads();
    for (int s = 128; s; s >>= 1) {
        if (t < s) { red[t] += red[t + s]; red2[t] += red2[t + s]; }
        __syncthreads();
    }
    float inv1 = (red[0]  > 0.f) ? 1.f / red[0]  : 0.f;
    float inv2 = (red2[0] > 0.f) ? 1.f / red2[0] : 0.f;

    // weighted accumulation of user_e over the list; 4 groups x 64 d-lanes.
    // Normalization folded into the final combine.
    int g = t >> 6;
    int d = t & 63;
    float o1 = 0.f, o2 = 0.f;
    int q = g;
    for (; q + 12 < L; q += 16) {
        int j0 = lst[q], j1 = lst[q + 4], j2 = lst[q + 8], j3 = lst[q + 12];
        float u0 = g_ue[j0 * 64 + d];
        float u1 = g_ue[j1 * 64 + d];
        float u2 = g_ue[j2 * 64 + d];
        float u3 = g_ue[j3 * 64 + d];
        o1 += rA[j0] * u0;  o2 += rA2[j0] * u0;
        o1 += rA[j1] * u1;  o2 += rA2[j1] * u1;
        o1 += rA[j2] * u2;  o2 += rA2[j2] * u2;
        o1 += rA[j3] * u3;  o2 += rA2[j3] * u3;
    }
    for (; q < L; q += 4) {
        int j = lst[q];
        float u = g_ue[j * 64 + d];
        o1 += rA[j] * u;
        o2 += rA2[j] * u;
    }
    sg1[g][d] = o1;
    sg2[g][d] = o2;
    __syncthreads();
    if (g == 0) {
        float t1 = sg1[0][d] + sg1[1][d] + sg1[2][d] + sg1[3][d];
        float t2 = sg2[0][d] + sg2[1][d] + sg2[2][d] + sg2[3][d];
        out[i * 64 + d] = (4.f / 3.f) * g_ue[i * 64 + d]
                        + (t1 * inv1 + t2 * inv2) * (1.f / 3.f);
    }
}

// ---------------- launch ----------------
extern "C" void kernel_launch(void* const* d_in, const int* in_sizes, int n_in,
                              void* d_out, int out_size) {
    const float* ue_in = (const float*)d_in[0];
    const float* ie_in = (const float*)d_in[1];
    const float* ivals = (const float*)d_in[2];
    const float* Wa    = (const float*)d_in[3];
    const float* Wb    = (const float*)d_in[4];
    const float* w1    = (const float*)d_in[5];
    const float* b1    = (const float*)d_in[6];
    const float* w2    = (const float*)d_in[7];
    const float* b2    = (const float*)d_in[8];
    const int* irows   = (const int*)d_in[9];
    const int* icols   = (const int*)d_in[10];
    const int* srows   = (const int*)d_in[11];
    const int* scols   = (const int*)d_in[12];
    float* out = (float*)d_out;

    int *p_cnt_i, *p_rptr_i, *p_cur_i, *p_col_i;
    int *p_cnt_s, *p_rptr_s, *p_cur_s, *p_col_s;
    float *p_val_i, *p_val_s, *p_ew;
    cudaGetSymbolAddress((void**)&p_cnt_i,  g_cnt_i);
    cudaGetSymbolAddress((void**)&p_rptr_i, g_rptr_i);
    cudaGetSymbolAddress((void**)&p_cur_i,  g_cur_i);
    cudaGetSymbolAddress((void**)&p_col_i,  g_colp_i);
    cudaGetSymbolAddress((void**)&p_val_i,  g_valp_i);
    cudaGetSymbolAddress((void**)&p_cnt_s,  g_cnt_s);
    cudaGetSymbolAddress((void**)&p_rptr_s, g_rptr_s);
    cudaGetSymbolAddress((void**)&p_cur_s,  g_cur_s);
    cudaGetSymbolAddress((void**)&p_col_s,  g_colp_s);
    cudaGetSymbolAddress((void**)&p_val_s,  g_valp_s);
    cudaGetSymbolAddress((void**)&p_ew,     g_ew);

    // interaction-graph CSR
    k_zero_counts<<<(NNODES + 256) / 256, 256>>>();
    k_hist<<<1024, 256>>>(irows, NEI, p_cnt_i);
    k_scan<<<1, 1024>>>(p_cnt_i, p_rptr_i, p_cur_i, NNODES);
    k_scatter<<<1024, 256>>>(irows, icols, ivals, NEI, p_cur_i, p_col_i, p_val_i);

    // LightGCN: 3 SpMM layers, mean over {h0..h3} of user rows
    k_init_h<<<(NNODES * DD + 255) / 256, 256>>>(ue_in, ie_in);
    k_spmm<<<NNODES / 4, dim3(64, 4)>>>(1);
    k_spmm<<<NNODES / 4, dim3(64, 4)>>>(0);
    k_spmm<<<NNODES / 4, dim3(64, 4)>>>(1);
    k_fin_ue<<<(UU * DD + 255) / 256, 256>>>();

    // social edge weights (fused MLP)
    k_kab<<<32, 256>>>(Wa, Wb, w1);
    k_pab<<<UU / 4, dim3(64, 4)>>>(ue_in, b1);
    k_edge<<<NES / 8, 256>>>(srows, scols, w2, b2);

    // social-graph CSR (weights = edge_w)
    k_hist<<<256, 256>>>(srows, NES, p_cnt_s);
    k_scan<<<1, 1024>>>(p_cnt_s, p_rptr_s, p_cur_s, UU);
    k_scatter<<<256, 256>>>(srows, scols, p_ew, NES, p_cur_s, p_col_s, p_val_s);

    // sparse masked-softmax propagation + final combine
    k_social<<<UU, 256>>>(out);
}

// round 5
// speedup vs baseline: 2.8489x; 1.1923x over previous
#include <cuda_runtime.h>
#include <math.h>

#define UU 4096
#define II 16384
#define DD 64
#define NNODES (UU + II)   // 20480
#define NEI 524288
#define NES 65536

// ---------------- device scratch (no allocation allowed) ----------------
__device__ float  g_h0[NNODES * DD];
__device__ float  g_h1[NNODES * DD];
__device__ float  g_acc[UU * DD];
__device__ float  g_ue[UU * DD];

__device__ int    g_cnt_i[NNODES + 1];
__device__ int    g_rptr_i[NNODES + 1];
__device__ int    g_cur_i[NNODES + 1];
__device__ float2 g_ep[NEI];            // packed (col-as-float-bits, val)

__device__ int    g_cnt_s[UU + 1];
__device__ int    g_rptr_s[UU + 1];
__device__ int    g_cur_s[UU + 1];
__device__ int    g_colp_s[NES];
__device__ float  g_valp_s[NES];
__device__ int    g_pos[NES];           // edge e -> CSR slot p

__device__ float  g_Ka[DD * DD];
__device__ float  g_Kb[DD * DD];
__device__ float  g_Pa[UU * DD];
__device__ float  g_Pb[UU * DD];

// ---------------- fused init: zero counts + stage h0/acc ----------------
__global__ void k_init(const float* __restrict__ ue_in, const float* __restrict__ ie_in) {
    int t = blockIdx.x * blockDim.x + threadIdx.x;   // covers NNODES*DD
    if (t <= NNODES) g_cnt_i[t] = 0;
    if (t <= UU)     g_cnt_s[t] = 0;
    if (t < UU * DD) {
        float v = ue_in[t];
        g_h0[t] = v;
        g_acc[t] = v;
    } else if (t < NNODES * DD) {
        g_h0[t] = ie_in[t - UU * DD];
    }
}

// ---------------- fused histograms ----------------
__global__ void k_hist_both(const int* __restrict__ irows, const int* __restrict__ srows) {
    int b = blockIdx.x;
    if (b < 1024) {
        for (int e = b * 256 + threadIdx.x; e < NEI; e += 1024 * 256)
            atomicAdd(&g_cnt_i[irows[e]], 1);
    } else {
        for (int e = (b - 1024) * 256 + threadIdx.x; e < NES; e += 128 * 256)
            atomicAdd(&g_cnt_s[srows[e]], 1);
    }
}

// ---------------- fused scans: register-resident chunks, warp-shuffle ----------------
template <int NCH>
__device__ void scan_impl(const int* __restrict__ cnt, int* rptr, int* cur, int n) {
    __shared__ int wsum[32];
    __shared__ int tot;
    int t = threadIdx.x, lane = t & 31, w = t >> 5;
    int v[NCH];
#pragma unroll
    for (int c = 0; c < NCH; c++) {
        int i = c * 1024 + t;
        v[c] = (i < n) ? cnt[i] : 0;
    }
    int off = 0;
#pragma unroll
    for (int c = 0; c < NCH; c++) {
        int x = v[c];
#pragma unroll
        for (int d = 1; d < 32; d <<= 1) {
            int y = __shfl_up_sync(0xffffffffu, x, d);
            if (lane >= d) x += y;
        }
        if (lane == 31) wsum[w] = x;
        __syncthreads();
        if (w == 0) {
            int s = wsum[lane];
            int xs = s;
#pragma unroll
            for (int d = 1; d < 32; d <<= 1) {
                int y = __shfl_up_sync(0xffffffffu, xs, d);
                if (lane >= d) xs += y;
            }
            wsum[lane] = xs - s;
            if (lane == 31) tot = xs;
        }
        __syncthreads();
        int excl = off + wsum[w] + x - v[c];
        int i = c * 1024 + t;
        if (i < n) { rptr[i] = excl; cur[i] = excl; }
        off += tot;
        __syncthreads();
    }
    if (t == 0) { rptr[n] = off; cur[n] = off; }
}

__global__ void k_scan_both() {
    if (blockIdx.x == 0)
        scan_impl<NNODES / 1024>(g_cnt_i, g_rptr_i, g_cur_i, NNODES);
    else
        scan_impl<UU / 1024>(g_cnt_s, g_rptr_s, g_cur_s, UU);
}

// ---------------- fused scatters ----------------
__global__ void k_scatter_both(const int* __restrict__ irows, const int* __restrict__ icols,
                               const float* __restrict__ ivals,
                               const int* __restrict__ srows, const int* __restrict__ scols) {
    int b = blockIdx.x;
    if (b < 1024) {
        for (int e = b * 256 + threadIdx.x; e < NEI; e += 1024 * 256) {
            int r = irows[e];
            int p = atomicAdd(&g_cur_i[r], 1);
            g_ep[p] = make_float2(__int_as_float(icols[e]), ivals[e]);
        }
    } else {
        for (int e = (b - 1024) * 256 + threadIdx.x; e < NES; e += 128 * 256) {
            int r = srows[e];
            int p = atomicAdd(&g_cur_s[r], 1);
            g_colp_s[p] = scols[e];
            g_pos[e] = p;
        }
    }
}

// ---------------- LightGCN SpMM: one row per 64 threads, 4 rows/block ----------------
__global__ void k_spmm(int srcIs0, int fin) {
    const float* __restrict__ src = srcIs0 ? g_h0 : g_h1;
    float* __restrict__ dst = srcIs0 ? g_h1 : g_h0;
    int row = blockIdx.x * 4 + threadIdx.y;
    int d = threadIdx.x;
    int b = g_rptr_i[row], e = g_rptr_i[row + 1];
    float a = 0.f;
    int k = b;
    for (; k + 3 < e; k += 4) {
        float2 e0 = g_ep[k],     e1 = g_ep[k + 1];
        float2 e2 = g_ep[k + 2], e3 = g_ep[k + 3];
        float x0 = src[__float_as_int(e0.x) * DD + d];
        float x1 = src[__float_as_int(e1.x) * DD + d];
        float x2 = src[__float_as_int(e2.x) * DD + d];
        float x3 = src[__float_as_int(e3.x) * DD + d];
        a += e0.y * x0; a += e1.y * x1; a += e2.y * x2; a += e3.y * x3;
    }
    for (; k < e; k++) {
        float2 ev = g_ep[k];
        a += ev.y * src[__float_as_int(ev.x) * DD + d];
    }
    if (fin) {
        if (row < UU) g_ue[row * DD + d] = (g_acc[row * DD + d] + a) * 0.25f;
    } else {
        dst[row * DD + d] = a;
        if (row < UU) g_acc[row * DD + d] += a;
    }
}

// ---------------- social edge MLP precompute ----------------
__global__ void k_kab(const float* __restrict__ Wa, const float* __restrict__ Wb,
                      const float* __restrict__ w1) {
    int t = blockIdx.x * blockDim.x + threadIdx.x;   // 8192
    int which = t >> 12;
    int idx = t & 4095;
    int k = idx >> 6, j = idx & 63;
    const float* W = which ? Wb : Wa;
    const float* w1p = which ? (w1 + 64 * 64) : w1;
    float s = 0.f;
#pragma unroll 8
    for (int m = 0; m < 64; m++) s += W[k * 64 + m] * w1p[m * 64 + j];
    if (which) g_Kb[idx] = s; else g_Ka[idx] = s;
}

__global__ void k_pab(const float* __restrict__ ue_in, const float* __restrict__ b1) {
    __shared__ float sKa[64 * 64];
    __shared__ float sKb[64 * 64];
    int t = threadIdx.y * 64 + threadIdx.x;
    for (int q = t; q < 4096; q += 256) { sKa[q] = g_Ka[q]; sKb[q] = g_Kb[q]; }
    __syncthreads();
    int i = blockIdx.x * 4 + threadIdx.y;
    int j = threadIdx.x;
    float a = 0.f, bb = 0.f;
#pragma unroll 8
    for (int k = 0; k < 64; k++) {
        float u = ue_in[i * 64 + k];
        a += u * sKa[k * 64 + j];
        bb += u * sKb[k * 64 + j];
    }
    g_Pa[i * 64 + j] = a;
    g_Pb[i * 64 + j] = bb + b1[j];
}

// edge MLP -> sigmoid, written straight into the CSR value slot
__global__ void k_edge(const int* __restrict__ srows, const int* __restrict__ scols,
                       const float* __restrict__ w2, const float* __restrict__ b2) {
    int warp = (blockIdx.x * blockDim.x + threadIdx.x) >> 5;
    int lane = threadIdx.x & 31;
    if (warp >= NES) return;
    int r = srows[warp], c = scols[warp];
    float h0 = g_Pa[c * 64 + lane] + g_Pb[r * 64 + lane];
    float h1 = g_Pa[c * 64 + 32 + lane] + g_Pb[r * 64 + 32 + lane];
    h0 = fmaxf(h0, 0.f);
    h1 = fmaxf(h1, 0.f);
    float p = h0 * w2[lane] + h1 * w2[lane + 32];
#pragma unroll
    for (int o = 16; o; o >>= 1) p += __shfl_down_sync(0xffffffffu, p, o);
    if (lane == 0)
        g_valp_s[g_pos[warp]] = 1.f / (1.f + __expf(-(p + b2[0])));
}

// ---------------- social propagation (sparse masked softmax), 512 threads ----------------
__global__ void __launch_bounds__(512) k_social(float* __restrict__ out) {
    __shared__ float rA[UU];             // 16 KB
    __shared__ float rA2[UU];            // 16 KB
    __shared__ unsigned short lst[UU];   // 8 KB
    __shared__ int nlst;
    __shared__ float wr1[16], wr2[16];
    __shared__ float bc1, bc2;
    __shared__ float sg1[8][64];         // 2 KB
    __shared__ float sg2[8][64];         // 2 KB

    int i = blockIdx.x;
    int t = threadIdx.x;   // 512
    int lane = t & 31, w = t >> 5;

    // zero rows (float4)
    float4* rA4 = (float4*)rA;
    float4* rB4 = (float4*)rA2;
    float4 z4 = make_float4(0.f, 0.f, 0.f, 0.f);
#pragma unroll
    for (int q = t; q < UU / 4; q += 512) { rA4[q] = z4; rB4[q] = z4; }
    if (t == 0) nlst = 0;
    __syncthreads();

    int b = g_rptr_s[i], e = g_rptr_s[i + 1];
    // depth-1: merged A row
    for (int k = b + t; k < e; k += 512)
        atomicAdd(&rA[g_colp_s[k]], g_valp_s[k]);
    // depth-2: A2[i,:] += w_ik * A[k,:]; 16 threads per neighbor, 32 in flight
    for (int k = b + (t >> 4); k < e; k += 32) {
        int kk = g_colp_s[k];
        float wv = g_valp_s[k];
        int b2i = g_rptr_s[kk], e2i = g_rptr_s[kk + 1];
        for (int m = b2i + (t & 15); m < e2i; m += 16)
            atomicAdd(&rA2[g_colp_s[m]], wv * g_valp_s[m]);
    }
    __syncthreads();

    // compact union of nonzero columns (warp-aggregated push); 4096/512 = 8 iters
#pragma unroll
    for (int j = t; j < UU; j += 512) {
        bool nz = (rA[j] > 0.f) || (rA2[j] > 0.f);
        unsigned mask = __ballot_sync(0xffffffffu, nz);
        if (nz) {
            int lead = __ffs(mask) - 1;
            int basep = 0;
            if (lane == lead) basep = atomicAdd(&nlst, __popc(mask));
            basep = __shfl_sync(mask, basep, lead);
            int off = __popc(mask & ((1u << lane) - 1u));
            lst[basep + off] = (unsigned short)j;
        }
    }
    __syncthreads();
    int L = nlst;

    // max over list (both rows), warp-shuffle reduction
    float m1 = -1e30f, m2 = -1e30f;
    for (int q = t; q < L; q += 512) {
        int j = lst[q];
        float a1 = rA[j], a2 = rA2[j];
        m1 = fmaxf(m1, a1 > 0.f ? a1 : -1e30f);
        m2 = fmaxf(m2, a2 > 0.f ? a2 : -1e30f);
    }
#pragma unroll
    for (int o = 16; o; o >>= 1) {
        m1 = fmaxf(m1, __shfl_xor_sync(0xffffffffu, m1, o));
        m2 = fmaxf(m2, __shfl_xor_sync(0xffffffffu, m2, o));
    }
    if (lane == 0) { wr1[w] = m1; wr2[w] = m2; }
    __syncthreads();
    if (w == 0 && lane < 16) {
        m1 = wr1[lane]; m2 = wr2[lane];
#pragma unroll
        for (int o = 8; o; o >>= 1) {
            m1 = fmaxf(m1, __shfl_xor_sync(0xffffu, m1, o));
            m2 = fmaxf(m2, __shfl_xor_sync(0xffffu, m2, o));
        }
        if (lane == 0) { bc1 = m1; bc2 = m2; }
    }
    __syncthreads();
    m1 = bc1; m2 = bc2;
    __syncthreads();

    // exp + sums (writeback; list entries unique)
    float s1 = 0.f, s2 = 0.f;
    for (int q = t; q < L; q += 512) {
        int j = lst[q];
        float a1 = rA[j], a2 = rA2[j];
        float e1 = (a1 > 0.f) ? __expf(a1 - m1) : 0.f;
        float e2 = (a2 > 0.f) ? __expf(a2 - m2) : 0.f;
        rA[j] = e1; rA2[j] = e2;
        s1 += e1; s2 += e2;
    }
#pragma unroll
    for (int o = 16; o; o >>= 1) {
        s1 += __shfl_xor_sync(0xffffffffu, s1, o);
        s2 += __shfl_xor_sync(0xffffffffu, s2, o);
    }
    if (lane == 0) { wr1[w] = s1; wr2[w] = s2; }
    __syncthreads();
    if (w == 0 && lane < 16) {
        s1 = wr1[lane]; s2 = wr2[lane];
#pragma unroll
        for (int o = 8; o; o >>= 1) {
            s1 += __shfl_xor_sync(0xffffu, s1, o);
            s2 += __shfl_xor_sync(0xffffu, s2, o);
        }
        if (lane == 0) { bc1 = s1; bc2 = s2; }
    }
    __syncthreads();
    float inv1 = (bc1 > 0.f) ? 1.f / bc1 : 0.f;
    float inv2 = (bc2 > 0.f) ? 1.f / bc2 : 0.f;

    // weighted accumulation of user_e over the list; 8 groups x 64 d-lanes
    int g = t >> 6;
    int d = t & 63;
    float o1 = 0.f, o2 = 0.f;
    int q = g;
    for (; q + 24 < L; q += 32) {
        int j0 = lst[q], j1 = lst[q + 8], j2 = lst[q + 16], j3 = lst[q + 24];
        float u0 = g_ue[j0 * 64 + d];
        float u1 = g_ue[j1 * 64 + d];
        float u2 = g_ue[j2 * 64 + d];
        float u3 = g_ue[j3 * 64 + d];
        o1 += rA[j0] * u0;  o2 += rA2[j0] * u0;
        o1 += rA[j1] * u1;  o2 += rA2[j1] * u1;
        o1 += rA[j2] * u2;  o2 += rA2[j2] * u2;
        o1 += rA[j3] * u3;  o2 += rA2[j3] * u3;
    }
    for (; q < L; q += 8) {
        int j = lst[q];
        float u = g_ue[j * 64 + d];
        o1 += rA[j] * u;
        o2 += rA2[j] * u;
    }
    sg1[g][d] = o1;
    sg2[g][d] = o2;
    __syncthreads();
    if (g == 0) {
        float t1 = 0.f, t2 = 0.f;
#pragma unroll
        for (int gg = 0; gg < 8; gg++) { t1 += sg1[gg][d]; t2 += sg2[gg][d]; }
        out[i * 64 + d] = (4.f / 3.f) * g_ue[i * 64 + d]
                        + (t1 * inv1 + t2 * inv2) * (1.f / 3.f);
    }
}

// ---------------- launch ----------------
extern "C" void kernel_launch(void* const* d_in, const int* in_sizes, int n_in,
                              void* d_out, int out_size) {
    const float* ue_in = (const float*)d_in[0];
    const float* ie_in = (const float*)d_in[1];
    const float* ivals = (const float*)d_in[2];
    const float* Wa    = (const float*)d_in[3];
    const float* Wb    = (const float*)d_in[4];
    const float* w1    = (const float*)d_in[5];
    const float* b1    = (const float*)d_in[6];
    const float* w2    = (const float*)d_in[7];
    const float* b2    = (const float*)d_in[8];
    const int* irows   = (const int*)d_in[9];
    const int* icols   = (const int*)d_in[10];
    const int* srows   = (const int*)d_in[11];
    const int* scols   = (const int*)d_in[12];
    float* out = (float*)d_out;

    // 1. fused zero + h0/acc staging
    k_init<<<(NNODES * DD + 255) / 256, 256>>>(ue_in, ie_in);
    // 2. both histograms
    k_hist_both<<<1024 + 128, 256>>>(irows, srows);
    // 3. both scans (2 independent blocks)
    k_scan_both<<<2, 1024>>>();
    // 4. both scatters (packed inter edges; social stores CSR slot per edge)
    k_scatter_both<<<1024 + 128, 256>>>(irows, icols, ivals, srows, scols);

    // 5-7. LightGCN: 3 SpMM layers; mean folded into the last
    k_spmm<<<NNODES / 4, dim3(64, 4)>>>(1, 0);
    k_spmm<<<NNODES / 4, dim3(64, 4)>>>(0, 0);
    k_spmm<<<NNODES / 4, dim3(64, 4)>>>(1, 1);

    // 8-10. social edge weights (fused MLP), written into CSR slots
    k_kab<<<32, 256>>>(Wa, Wb, w1);
    k_pab<<<UU / 4, dim3(64, 4)>>>(ue_in, b1);
    k_edge<<<NES / 8, 256>>>(srows, scols, w2, b2);

    // 11. sparse masked-softmax propagation + final combine
    k_social<<<UU, 512>>>(out);
}

// round 6
// speedup vs baseline: 3.0402x; 1.0671x over previous
#include <cuda_runtime.h>
#include <math.h>

#define UU 4096
#define II 16384
#define DD 64
#define NNODES (UU + II)   // 20480
#define NEI 524288
#define NES 65536

// ---------------- device scratch (no allocation allowed) ----------------
__device__ float  g_h1[NNODES * DD];    // layer-1 output
__device__ float  g_h2[NNODES * DD];    // layer-2 output
__device__ float  g_acc[UU * DD];       // running sum h0+h1+h2 (user rows)
__device__ float  g_ue[UU * DD];        // final lightgcn user embedding

__device__ int    g_cnt_i[NNODES + 1];
__device__ int    g_rptr_i[NNODES + 1];
__device__ int    g_cur_i[NNODES + 1];
__device__ float2 g_ep[NEI];            // packed (col-as-float-bits, val)

__device__ int    g_cnt_s[UU + 1];
__device__ int    g_rptr_s[UU + 1];
__device__ int    g_cur_s[UU + 1];
__device__ int    g_colp_s[NES];
__device__ float  g_valp_s[NES];

__device__ float  g_Ka[DD * DD];
__device__ float  g_Kb[DD * DD];
__device__ float  g_Pa[UU * DD];
__device__ float  g_Pb[UU * DD];

// ---------------- 1. zero counters + Ka/Kb GEMM (independent work) ----------------
__global__ void k_zero_kab(const float* __restrict__ Wa, const float* __restrict__ Wb,
                           const float* __restrict__ w1) {
    int b = blockIdx.x;
    if (b < 81) {
        int t = b * 256 + threadIdx.x;
        if (t <= NNODES) g_cnt_i[t] = 0;
        if (t <= UU)     g_cnt_s[t] = 0;
    } else {
        int t = (b - 81) * 256 + threadIdx.x;   // 0..8191
        int which = t >> 12;
        int idx = t & 4095;
        int k = idx >> 6, j = idx & 63;
        const float* W = which ? Wb : Wa;
        const float* w1p = which ? (w1 + 64 * 64) : w1;
        float s = 0.f;
#pragma unroll 8
        for (int m = 0; m < 64; m++) s += W[k * 64 + m] * w1p[m * 64 + j];
        if (which) g_Kb[idx] = s; else g_Ka[idx] = s;
    }
}

// ---------------- 2. both histograms + Pa/Pb GEMM ----------------
__global__ void k_hist_pab(const int* __restrict__ irows, const int* __restrict__ srows,
                           const float* __restrict__ ue_in, const float* __restrict__ b1) {
    int b = blockIdx.x;
    if (b < 1024) {
        for (int e = b * 256 + threadIdx.x; e < NEI; e += 1024 * 256)
            atomicAdd(&g_cnt_i[irows[e]], 1);
    } else if (b < 1152) {
        for (int e = (b - 1024) * 256 + threadIdx.x; e < NES; e += 128 * 256)
            atomicAdd(&g_cnt_s[srows[e]], 1);
    } else {
        // Pa = U@Ka ; Pb = U@Kb + b1 ; 16 rows per block, 256 blocks
        __shared__ float sKa[64 * 64];
        __shared__ float sKb[64 * 64];
        int t = threadIdx.x;
        for (int q = t; q < 4096; q += 256) { sKa[q] = g_Ka[q]; sKb[q] = g_Kb[q]; }
        __syncthreads();
        int j = t & 63;
        int isub = t >> 6;
        int i0 = (b - 1152) * 16;
        for (int ii = isub; ii < 16; ii += 4) {
            int i = i0 + ii;
            float a = 0.f, bb = 0.f;
#pragma unroll 8
            for (int k = 0; k < 64; k++) {
                float u = ue_in[i * 64 + k];
                a += u * sKa[k * 64 + j];
                bb += u * sKb[k * 64 + j];
            }
            g_Pa[i * 64 + j] = a;
            g_Pb[i * 64 + j] = bb + b1[j];
        }
    }
}

// ---------------- 3. both scans ----------------
template <int NCH>
__device__ void scan_impl(const int* __restrict__ cnt, int* rptr, int* cur, int n) {
    __shared__ int wsum[32];
    __shared__ int tot;
    int t = threadIdx.x, lane = t & 31, w = t >> 5;
    int v[NCH];
#pragma unroll
    for (int c = 0; c < NCH; c++) {
        int i = c * 1024 + t;
        v[c] = (i < n) ? cnt[i] : 0;
    }
    int off = 0;
#pragma unroll
    for (int c = 0; c < NCH; c++) {
        int x = v[c];
#pragma unroll
        for (int d = 1; d < 32; d <<= 1) {
            int y = __shfl_up_sync(0xffffffffu, x, d);
            if (lane >= d) x += y;
        }
        if (lane == 31) wsum[w] = x;
        __syncthreads();
        if (w == 0) {
            int s = wsum[lane];
            int xs = s;
#pragma unroll
            for (int d = 1; d < 32; d <<= 1) {
                int y = __shfl_up_sync(0xffffffffu, xs, d);
                if (lane >= d) xs += y;
            }
            wsum[lane] = xs - s;
            if (lane == 31) tot = xs;
        }
        __syncthreads();
        int excl = off + wsum[w] + x - v[c];
        int i = c * 1024 + t;
        if (i < n) { rptr[i] = excl; cur[i] = excl; }
        off += tot;
        __syncthreads();
    }
    if (t == 0) { rptr[n] = off; cur[n] = off; }
}

__global__ void k_scan_both() {
    if (blockIdx.x == 0)
        scan_impl<NNODES / 1024>(g_cnt_i, g_rptr_i, g_cur_i, NNODES);
    else
        scan_impl<UU / 1024>(g_cnt_s, g_rptr_s, g_cur_s, UU);
}

// ---------------- 4. scatters + fused social edge MLP ----------------
__global__ void k_scatter_edge(const int* __restrict__ irows, const int* __restrict__ icols,
                               const float* __restrict__ ivals,
                               const int* __restrict__ srows, const int* __restrict__ scols,
                               const float* __restrict__ w2, const float* __restrict__ b2) {
    int b = blockIdx.x;
    if (b < 1024) {
        for (int e = b * 256 + threadIdx.x; e < NEI; e += 1024 * 256) {
            int r = irows[e];
            int p = atomicAdd(&g_cur_i[r], 1);
            g_ep[p] = make_float2(__int_as_float(icols[e]), ivals[e]);
        }
    } else {
        // social: scatter structure AND compute sigmoid edge weight in-place.
        int lane = threadIdx.x & 31;
        float w2lo = w2[lane], w2hi = w2[lane + 32];
        float bias = b2[0];
        for (int e = (b - 1024) * 256 + threadIdx.x; e < NES; e += 128 * 256) {
            int r = srows[e];
            int c = scols[e];
            int p = atomicAdd(&g_cur_s[r], 1);
            g_colp_s[p] = c;
            // warp-cooperative MLP over the 32 lanes' edges
            for (int sl = 0; sl < 32; sl++) {
                int rr = __shfl_sync(0xffffffffu, r, sl);
                int cc = __shfl_sync(0xffffffffu, c, sl);
                int pp = __shfl_sync(0xffffffffu, p, sl);
                float h0 = g_Pa[cc * 64 + lane] + g_Pb[rr * 64 + lane];
                float h1 = g_Pa[cc * 64 + 32 + lane] + g_Pb[rr * 64 + 32 + lane];
                h0 = fmaxf(h0, 0.f);
                h1 = fmaxf(h1, 0.f);
                float pv = h0 * w2lo + h1 * w2hi;
#pragma unroll
                for (int o = 16; o; o >>= 1) pv += __shfl_down_sync(0xffffffffu, pv, o);
                if (lane == 0)
                    g_valp_s[pp] = 1.f / (1.f + __expf(-(pv + bias)));
            }
        }
    }
}

// ---------------- 5-7. LightGCN SpMM: 32 lanes x float2 per row, 8 rows/block ----------------
template <int LAYER>
__global__ void k_spmm(const float2* __restrict__ uin2, const float2* __restrict__ iin2) {
    int row = blockIdx.x * 8 + threadIdx.y;
    int lane = threadIdx.x;
    const float2* __restrict__ s1 = (const float2*)g_h1;
    const float2* __restrict__ s2 = (const float2*)g_h2;
    float2* __restrict__ acc2 = (float2*)g_acc;

    int b = g_rptr_i[row], e = g_rptr_i[row + 1];
    float ax = 0.f, ay = 0.f;

    auto fetch = [&](int c) -> float2 {
        if (LAYER == 1) return (c < UU) ? uin2[c * 32 + lane] : iin2[(c - UU) * 32 + lane];
        else if (LAYER == 2) return s1[c * 32 + lane];
        else return s2[c * 32 + lane];
    };

    int k = b;
    for (; k + 3 < e; k += 4) {
        float2 e0 = g_ep[k],     e1 = g_ep[k + 1];
        float2 e2 = g_ep[k + 2], e3 = g_ep[k + 3];
        float2 x0 = fetch(__float_as_int(e0.x));
        float2 x1 = fetch(__float_as_int(e1.x));
        float2 x2 = fetch(__float_as_int(e2.x));
        float2 x3 = fetch(__float_as_int(e3.x));
        ax += e0.y * x0.x; ay += e0.y * x0.y;
        ax += e1.y * x1.x; ay += e1.y * x1.y;
        ax += e2.y * x2.x; ay += e2.y * x2.y;
        ax += e3.y * x3.x; ay += e3.y * x3.y;
    }
    for (; k < e; k++) {
        float2 ev = g_ep[k];
        float2 x = fetch(__float_as_int(ev.x));
        ax += ev.y * x.x; ay += ev.y * x.y;
    }

    int o = row * 32 + lane;
    if (LAYER == 1) {
        ((float2*)g_h1)[o] = make_float2(ax, ay);
        if (row < UU) {
            float2 u = uin2[o];
            acc2[o] = make_float2(u.x + ax, u.y + ay);
        }
    } else if (LAYER == 2) {
        ((float2*)g_h2)[o] = make_float2(ax, ay);
        if (row < UU) {
            float2 a = acc2[o];
            acc2[o] = make_float2(a.x + ax, a.y + ay);
        }
    } else {
        // user rows only (grid = UU/8)
        float2 a = acc2[o];
        ((float2*)g_ue)[o] = make_float2((a.x + ax) * 0.25f, (a.y + ay) * 0.25f);
    }
}

// ---------------- 8. social propagation (sparse masked softmax), 512 threads ----------------
__global__ void __launch_bounds__(512) k_social(float2* __restrict__ out2) {
    __shared__ float rA[UU];             // 16 KB
    __shared__ float rA2[UU];            // 16 KB
    __shared__ unsigned short lst[UU];   // 8 KB
    __shared__ int nlst;
    __shared__ float wr1[16], wr2[16];
    __shared__ float bc1, bc2;
    __shared__ float2 sg1[16][32];       // 4 KB
    __shared__ float2 sg2[16][32];       // 4 KB

    int i = blockIdx.x;
    int t = threadIdx.x;   // 512
    int lane = t & 31, w = t >> 5;

    float4* rA4 = (float4*)rA;
    float4* rB4 = (float4*)rA2;
    float4 z4 = make_float4(0.f, 0.f, 0.f, 0.f);
#pragma unroll
    for (int q = t; q < UU / 4; q += 512) { rA4[q] = z4; rB4[q] = z4; }
    if (t == 0) nlst = 0;
    __syncthreads();

    int b = g_rptr_s[i], e = g_rptr_s[i + 1];
    // depth-1 merged row
    for (int k = b + t; k < e; k += 512)
        atomicAdd(&rA[g_colp_s[k]], g_valp_s[k]);
    // depth-2: 16 threads per neighbor
    for (int k = b + (t >> 4); k < e; k += 32) {
        int kk = g_colp_s[k];
        float wv = g_valp_s[k];
        int b2i = g_rptr_s[kk], e2i = g_rptr_s[kk + 1];
        for (int m = b2i + (t & 15); m < e2i; m += 16)
            atomicAdd(&rA2[g_colp_s[m]], wv * g_valp_s[m]);
    }
    __syncthreads();

    // compaction fused with max computation
    float m1 = -1e30f, m2 = -1e30f;
#pragma unroll
    for (int j = t; j < UU; j += 512) {
        float a1 = rA[j], a2 = rA2[j];
        bool nz = (a1 > 0.f) || (a2 > 0.f);
        m1 = fmaxf(m1, a1 > 0.f ? a1 : -1e30f);
        m2 = fmaxf(m2, a2 > 0.f ? a2 : -1e30f);
        unsigned mask = __ballot_sync(0xffffffffu, nz);
        if (nz) {
            int lead = __ffs(mask) - 1;
            int basep = 0;
            if (lane == lead) basep = atomicAdd(&nlst, __popc(mask));
            basep = __shfl_sync(mask, basep, lead);
            int off = __popc(mask & ((1u << lane) - 1u));
            lst[basep + off] = (unsigned short)j;
        }
    }
#pragma unroll
    for (int o = 16; o; o >>= 1) {
        m1 = fmaxf(m1, __shfl_xor_sync(0xffffffffu, m1, o));
        m2 = fmaxf(m2, __shfl_xor_sync(0xffffffffu, m2, o));
    }
    if (lane == 0) { wr1[w] = m1; wr2[w] = m2; }
    __syncthreads();
    if (w == 0 && lane < 16) {
        m1 = wr1[lane]; m2 = wr2[lane];
#pragma unroll
        for (int o = 8; o; o >>= 1) {
            m1 = fmaxf(m1, __shfl_xor_sync(0xffffu, m1, o));
            m2 = fmaxf(m2, __shfl_xor_sync(0xffffu, m2, o));
        }
        if (lane == 0) { bc1 = m1; bc2 = m2; }
    }
    __syncthreads();
    m1 = bc1; m2 = bc2;
    int L = nlst;
    __syncthreads();

    // exp + sums (writeback; list entries unique)
    float s1 = 0.f, s2 = 0.f;
    for (int q = t; q < L; q += 512) {
        int j = lst[q];
        float a1 = rA[j], a2 = rA2[j];
        float e1 = (a1 > 0.f) ? __expf(a1 - m1) : 0.f;
        float e2 = (a2 > 0.f) ? __expf(a2 - m2) : 0.f;
        rA[j] = e1; rA2[j] = e2;
        s1 += e1; s2 += e2;
    }
#pragma unroll
    for (int o = 16; o; o >>= 1) {
        s1 += __shfl_xor_sync(0xffffffffu, s1, o);
        s2 += __shfl_xor_sync(0xffffffffu, s2, o);
    }
    if (lane == 0) { wr1[w] = s1; wr2[w] = s2; }
    __syncthreads();
    if (w == 0 && lane < 16) {
        s1 = wr1[lane]; s2 = wr2[lane];
#pragma unroll
        for (int o = 8; o; o >>= 1) {
            s1 += __shfl_xor_sync(0xffffu, s1, o);
            s2 += __shfl_xor_sync(0xffffu, s2, o);
        }
        if (lane == 0) { bc1 = s1; bc2 = s2; }
    }
    __syncthreads();
    float inv1 = (bc1 > 0.f) ? 1.f / bc1 : 0.f;
    float inv2 = (bc2 > 0.f) ? 1.f / bc2 : 0.f;

    // weighted accumulation over list; 16 groups x 32 lanes x float2
    const float2* __restrict__ ue2 = (const float2*)g_ue;
    int g = w;  // 16 groups of one warp each
    float2 o1 = make_float2(0.f, 0.f), o2 = make_float2(0.f, 0.f);
    int q = g;
    for (; q + 48 < L; q += 64) {
        int j0 = lst[q], j1 = lst[q + 16], j2 = lst[q + 32], j3 = lst[q + 48];
        float2 u0 = ue2[j0 * 32 + lane];
        float2 u1 = ue2[j1 * 32 + lane];
        float2 u2 = ue2[j2 * 32 + lane];
        float2 u3 = ue2[j3 * 32 + lane];
        float p10 = rA[j0], p20 = rA2[j0];
        float p11 = rA[j1], p21 = rA2[j1];
        float p12 = rA[j2], p22 = rA2[j2];
        float p13 = rA[j3], p23 = rA2[j3];
        o1.x += p10 * u0.x; o1.y += p10 * u0.y; o2.x += p20 * u0.x; o2.y += p20 * u0.y;
        o1.x += p11 * u1.x; o1.y += p11 * u1.y; o2.x += p21 * u1.x; o2.y += p21 * u1.y;
        o1.x += p12 * u2.x; o1.y += p12 * u2.y; o2.x += p22 * u2.x; o2.y += p22 * u2.y;
        o1.x += p13 * u3.x; o1.y += p13 * u3.y; o2.x += p23 * u3.x; o2.y += p23 * u3.y;
    }
    for (; q < L; q += 16) {
        int j = lst[q];
        float2 u = ue2[j * 32 + lane];
        float p1 = rA[j], p2 = rA2[j];
        o1.x += p1 * u.x; o1.y += p1 * u.y;
        o2.x += p2 * u.x; o2.y += p2 * u.y;
    }
    sg1[g][lane] = o1;
    sg2[g][lane] = o2;
    __syncthreads();
    if (t < 32) {
        float t1x = 0.f, t1y = 0.f, t2x = 0.f, t2y = 0.f;
#pragma unroll
        for (int gg = 0; gg < 16; gg++) {
            t1x += sg1[gg][lane].x; t1y += sg1[gg][lane].y;
            t2x += sg2[gg][lane].x; t2y += sg2[gg][lane].y;
        }
        float2 u = ue2[i * 32 + lane];
        out2[i * 32 + lane] = make_float2(
            (4.f / 3.f) * u.x + (t1x * inv1 + t2x * inv2) * (1.f / 3.f),
            (4.f / 3.f) * u.y + (t1y * inv1 + t2y * inv2) * (1.f / 3.f));
    }
}

// ---------------- launch ----------------
extern "C" void kernel_launch(void* const* d_in, const int* in_sizes, int n_in,
                              void* d_out, int out_size) {
    const float* ue_in = (const float*)d_in[0];
    const float* ie_in = (const float*)d_in[1];
    const float* ivals = (const float*)d_in[2];
    const float* Wa    = (const float*)d_in[3];
    const float* Wb    = (const float*)d_in[4];
    const float* w1    = (const float*)d_in[5];
    const float* b1    = (const float*)d_in[6];
    const float* w2    = (const float*)d_in[7];
    const float* b2    = (const float*)d_in[8];
    const int* irows   = (const int*)d_in[9];
    const int* icols   = (const int*)d_in[10];
    const int* srows   = (const int*)d_in[11];
    const int* scols   = (const int*)d_in[12];

    k_zero_kab<<<81 + 32, 256>>>(Wa, Wb, w1);
    k_hist_pab<<<1024 + 128 + 256, 256>>>(irows, srows, ue_in, b1);
    k_scan_both<<<2, 1024>>>();
    k_scatter_edge<<<1024 + 128, 256>>>(irows, icols, ivals, srows, scols, w2, b2);

    k_spmm<1><<<NNODES / 8, dim3(32, 8)>>>((const float2*)ue_in, (const float2*)ie_in);
    k_spmm<2><<<NNODES / 8, dim3(32, 8)>>>((const float2*)ue_in, (const float2*)ie_in);
    k_spmm<3><<<UU / 8,     dim3(32, 8)>>>((const float2*)ue_in, (const float2*)ie_in);

    k_social<<<UU, 512>>>((float2*)d_out);
}

// round 7
// speedup vs baseline: 3.4930x; 1.1490x over previous
#include <cuda_runtime.h>
#include <math.h>

#define UU 4096
#define II 16384
#define DD 64
#define NNODES (UU + II)   // 20480
#define NEI 524288
#define NES 65536

// ---------------- device scratch (no allocation allowed) ----------------
__device__ float  g_h1[NNODES * DD];    // layer-1 output
__device__ float  g_h2[NNODES * DD];    // layer-2 output
__device__ float  g_acc[UU * DD];       // running sum h0+h1+h2 (user rows)
__device__ float  g_ue[UU * DD];        // final lightgcn user embedding

__device__ int    g_cnt_i[NNODES + 1];
__device__ int    g_rptr_i[NNODES + 1];
__device__ int    g_cur_i[NNODES + 1];
__device__ float2 g_ep[NEI];            // packed (col-as-float-bits, val)

__device__ int    g_cnt_s[UU + 1];
__device__ int    g_rptr_s[UU + 1];
__device__ int    g_cur_s[UU + 1];
__device__ int    g_colp_s[NES];
__device__ float  g_valp_s[NES];
__device__ float  g_ew[NES];            // per-edge sigmoid weight

__device__ float  g_Ka[DD * DD];
__device__ float  g_Kb[DD * DD];
__device__ float  g_Pa[UU * DD];
__device__ float  g_Pb[UU * DD];

// ---------------- 1. zero counters + Ka/Kb GEMM (independent work) ----------------
__global__ void k_zero_kab(const float* __restrict__ Wa, const float* __restrict__ Wb,
                           const float* __restrict__ w1) {
    int b = blockIdx.x;
    if (b < 81) {
        int t = b * 256 + threadIdx.x;
        if (t <= NNODES) g_cnt_i[t] = 0;
        if (t <= UU)     g_cnt_s[t] = 0;
    } else {
        int t = (b - 81) * 256 + threadIdx.x;   // 0..8191
        int which = t >> 12;
        int idx = t & 4095;
        int k = idx >> 6, j = idx & 63;
        const float* W = which ? Wb : Wa;
        const float* w1p = which ? (w1 + 64 * 64) : w1;
        float s = 0.f;
#pragma unroll 8
        for (int m = 0; m < 64; m++) s += W[k * 64 + m] * w1p[m * 64 + j];
        if (which) g_Kb[idx] = s; else g_Ka[idx] = s;
    }
}

// ---------------- 2. both histograms + Pa/Pb GEMM ----------------
__global__ void k_hist_pab(const int* __restrict__ irows, const int* __restrict__ srows,
                           const float* __restrict__ ue_in, const float* __restrict__ b1) {
    int b = blockIdx.x;
    if (b < 1024) {
        for (int e = b * 256 + threadIdx.x; e < NEI; e += 1024 * 256)
            atomicAdd(&g_cnt_i[irows[e]], 1);
    } else if (b < 1152) {
        for (int e = (b - 1024) * 256 + threadIdx.x; e < NES; e += 128 * 256)
            atomicAdd(&g_cnt_s[srows[e]], 1);
    } else {
        // Pa = U@Ka ; Pb = U@Kb + b1 ; 16 rows per block, 256 blocks
        __shared__ float sKa[64 * 64];
        __shared__ float sKb[64 * 64];
        int t = threadIdx.x;
        for (int q = t; q < 4096; q += 256) { sKa[q] = g_Ka[q]; sKb[q] = g_Kb[q]; }
        __syncthreads();
        int j = t & 63;
        int isub = t >> 6;
        int i0 = (b - 1152) * 16;
        for (int ii = isub; ii < 16; ii += 4) {
            int i = i0 + ii;
            float a = 0.f, bb = 0.f;
#pragma unroll 8
            for (int k = 0; k < 64; k++) {
                float u = ue_in[i * 64 + k];
                a += u * sKa[k * 64 + j];
                bb += u * sKb[k * 64 + j];
            }
            g_Pa[i * 64 + j] = a;
            g_Pb[i * 64 + j] = bb + b1[j];
        }
    }
}

// ---------------- 3. both scans + parallel edge MLP ----------------
template <int NCH>
__device__ void scan_impl(const int* __restrict__ cnt, int* rptr, int* cur, int n) {
    __shared__ int wsum[32];
    __shared__ int tot;
    int t = threadIdx.x, lane = t & 31, w = t >> 5;
    int v[NCH];
#pragma unroll
    for (int c = 0; c < NCH; c++) {
        int i = c * 1024 + t;
        v[c] = (i < n) ? cnt[i] : 0;
    }
    int off = 0;
#pragma unroll
    for (int c = 0; c < NCH; c++) {
        int x = v[c];
#pragma unroll
        for (int d = 1; d < 32; d <<= 1) {
            int y = __shfl_up_sync(0xffffffffu, x, d);
            if (lane >= d) x += y;
        }
        if (lane == 31) wsum[w] = x;
        __syncthreads();
        if (w == 0) {
            int s = wsum[lane];
            int xs = s;
#pragma unroll
            for (int d = 1; d < 32; d <<= 1) {
                int y = __shfl_up_sync(0xffffffffu, xs, d);
                if (lane >= d) xs += y;
            }
            wsum[lane] = xs - s;
            if (lane == 31) tot = xs;
        }
        __syncthreads();
        int excl = off + wsum[w] + x - v[c];
        int i = c * 1024 + t;
        if (i < n) { rptr[i] = excl; cur[i] = excl; }
        off += tot;
        __syncthreads();
    }
    if (t == 0) { rptr[n] = off; cur[n] = off; }
}

__global__ void k_scan_edge(const int* __restrict__ srows, const int* __restrict__ scols,
                            const float* __restrict__ w2, const float* __restrict__ b2) {
    int b = blockIdx.x;
    if (b == 0) {
        scan_impl<NNODES / 1024>(g_cnt_i, g_rptr_i, g_cur_i, NNODES);
    } else if (b == 1) {
        scan_impl<UU / 1024>(g_cnt_s, g_rptr_s, g_cur_s, UU);
    } else {
        // edge MLP, one warp per edge: hid dims (2*lane, 2*lane+1) per lane
        int lane = threadIdx.x & 31;
        int wg = (b - 2) * 32 + (threadIdx.x >> 5);   // 256 blocks * 32 warps = 8192
        const float2* __restrict__ Pa2 = (const float2*)g_Pa;
        const float2* __restrict__ Pb2 = (const float2*)g_Pb;
        float2 wv = ((const float2*)w2)[lane];
        float bias = b2[0];
        for (int e = wg; e < NES; e += 8192) {
            int r = srows[e], c = scols[e];
            float2 pa = Pa2[c * 32 + lane];
            float2 pb = Pb2[r * 32 + lane];
            float h0 = fmaxf(pa.x + pb.x, 0.f);
            float h1 = fmaxf(pa.y + pb.y, 0.f);
            float pv = h0 * wv.x + h1 * wv.y;
#pragma unroll
            for (int o = 16; o; o >>= 1) pv += __shfl_down_sync(0xffffffffu, pv, o);
            if (lane == 0) g_ew[e] = 1.f / (1.f + __expf(-(pv + bias)));
        }
    }
}

// ---------------- 4. both scatters ----------------
__global__ void k_scatter_both(const int* __restrict__ irows, const int* __restrict__ icols,
                               const float* __restrict__ ivals,
                               const int* __restrict__ srows, const int* __restrict__ scols) {
    int b = blockIdx.x;
    if (b < 1024) {
        for (int e = b * 256 + threadIdx.x; e < NEI; e += 1024 * 256) {
            int r = irows[e];
            int p = atomicAdd(&g_cur_i[r], 1);
            g_ep[p] = make_float2(__int_as_float(icols[e]), ivals[e]);
        }
    } else {
        for (int e = (b - 1024) * 256 + threadIdx.x; e < NES; e += 128 * 256) {
            int r = srows[e];
            int p = atomicAdd(&g_cur_s[r], 1);
            g_colp_s[p] = scols[e];
            g_valp_s[p] = g_ew[e];
        }
    }
}

// ---------------- 5-7. LightGCN SpMM: 32 lanes x float2 per row, 8 rows/block ----------------
template <int LAYER>
__global__ void k_spmm(const float2* __restrict__ uin2, const float2* __restrict__ iin2) {
    int row = blockIdx.x * 8 + threadIdx.y;
    int lane = threadIdx.x;
    const float2* __restrict__ s1 = (const float2*)g_h1;
    const float2* __restrict__ s2 = (const float2*)g_h2;
    float2* __restrict__ acc2 = (float2*)g_acc;

    int b = g_rptr_i[row], e = g_rptr_i[row + 1];
    float ax = 0.f, ay = 0.f;

    auto fetch = [&](int c) -> float2 {
        if (LAYER == 1) return (c < UU) ? uin2[c * 32 + lane] : iin2[(c - UU) * 32 + lane];
        else if (LAYER == 2) return s1[c * 32 + lane];
        else return s2[c * 32 + lane];
    };

    int k = b;
    for (; k + 3 < e; k += 4) {
        float2 e0 = g_ep[k],     e1 = g_ep[k + 1];
        float2 e2 = g_ep[k + 2], e3 = g_ep[k + 3];
        float2 x0 = fetch(__float_as_int(e0.x));
        float2 x1 = fetch(__float_as_int(e1.x));
        float2 x2 = fetch(__float_as_int(e2.x));
        float2 x3 = fetch(__float_as_int(e3.x));
        ax += e0.y * x0.x; ay += e0.y * x0.y;
        ax += e1.y * x1.x; ay += e1.y * x1.y;
        ax += e2.y * x2.x; ay += e2.y * x2.y;
        ax += e3.y * x3.x; ay += e3.y * x3.y;
    }
    for (; k < e; k++) {
        float2 ev = g_ep[k];
        float2 x = fetch(__float_as_int(ev.x));
        ax += ev.y * x.x; ay += ev.y * x.y;
    }

    int o = row * 32 + lane;
    if (LAYER == 1) {
        ((float2*)g_h1)[o] = make_float2(ax, ay);
        if (row < UU) {
            float2 u = uin2[o];
            acc2[o] = make_float2(u.x + ax, u.y + ay);
        }
    } else if (LAYER == 2) {
        ((float2*)g_h2)[o] = make_float2(ax, ay);
        if (row < UU) {
            float2 a = acc2[o];
            acc2[o] = make_float2(a.x + ax, a.y + ay);
        }
    } else {
        // user rows only (grid = UU/8)
        float2 a = acc2[o];
        ((float2*)g_ue)[o] = make_float2((a.x + ax) * 0.25f, (a.y + ay) * 0.25f);
    }
}

// ---------------- 8. social propagation (sparse masked softmax), 512 threads ----------------
__global__ void __launch_bounds__(512) k_social(float2* __restrict__ out2) {
    __shared__ float rA[UU];             // 16 KB
    __shared__ float rA2[UU];            // 16 KB
    __shared__ unsigned short lst[UU];   // 8 KB
    __shared__ int nlst;
    __shared__ float wr1[16], wr2[16];
    __shared__ float bc1, bc2;
    __shared__ float2 sg[16][32];        // 4 KB

    int i = blockIdx.x;
    int t = threadIdx.x;   // 512
    int lane = t & 31, w = t >> 5;

    float4* rA4 = (float4*)rA;
    float4* rB4 = (float4*)rA2;
    float4 z4 = make_float4(0.f, 0.f, 0.f, 0.f);
#pragma unroll
    for (int q = t; q < UU / 4; q += 512) { rA4[q] = z4; rB4[q] = z4; }
    if (t == 0) nlst = 0;
    __syncthreads();

    int b = g_rptr_s[i], e = g_rptr_s[i + 1];
    // depth-1 merged row
    for (int k = b + t; k < e; k += 512)
        atomicAdd(&rA[g_colp_s[k]], g_valp_s[k]);
    // depth-2: 16 threads per neighbor
    for (int k = b + (t >> 4); k < e; k += 32) {
        int kk = g_colp_s[k];
        float wv = g_valp_s[k];
        int b2i = g_rptr_s[kk], e2i = g_rptr_s[kk + 1];
        for (int m = b2i + (t & 15); m < e2i; m += 16)
            atomicAdd(&rA2[g_colp_s[m]], wv * g_valp_s[m]);
    }
    __syncthreads();

    // compaction fused with max computation
    float m1 = -1e30f, m2 = -1e30f;
#pragma unroll
    for (int j = t; j < UU; j += 512) {
        float a1 = rA[j], a2 = rA2[j];
        bool nz = (a1 > 0.f) || (a2 > 0.f);
        m1 = fmaxf(m1, a1 > 0.f ? a1 : -1e30f);
        m2 = fmaxf(m2, a2 > 0.f ? a2 : -1e30f);
        unsigned mask = __ballot_sync(0xffffffffu, nz);
        if (nz) {
            int lead = __ffs(mask) - 1;
            int basep = 0;
            if (lane == lead) basep = atomicAdd(&nlst, __popc(mask));
            basep = __shfl_sync(mask, basep, lead);
            int off = __popc(mask & ((1u << lane) - 1u));
            lst[basep + off] = (unsigned short)j;
        }
    }
#pragma unroll
    for (int o = 16; o; o >>= 1) {
        m1 = fmaxf(m1, __shfl_xor_sync(0xffffffffu, m1, o));
        m2 = fmaxf(m2, __shfl_xor_sync(0xffffffffu, m2, o));
    }
    if (lane == 0) { wr1[w] = m1; wr2[w] = m2; }
    __syncthreads();
    if (w == 0 && lane < 16) {
        m1 = wr1[lane]; m2 = wr2[lane];
#pragma unroll
        for (int o = 8; o; o >>= 1) {
            m1 = fmaxf(m1, __shfl_xor_sync(0xffffu, m1, o));
            m2 = fmaxf(m2, __shfl_xor_sync(0xffffu, m2, o));
        }
        if (lane == 0) { bc1 = m1; bc2 = m2; }
    }
    __syncthreads();
    m1 = bc1; m2 = bc2;
    int L = nlst;
    __syncthreads();

    // exp + sums (writeback; list entries unique)
    float s1 = 0.f, s2 = 0.f;
    for (int q = t; q < L; q += 512) {
        int j = lst[q];
        float a1 = rA[j], a2 = rA2[j];
        float e1 = (a1 > 0.f) ? __expf(a1 - m1) : 0.f;
        float e2 = (a2 > 0.f) ? __expf(a2 - m2) : 0.f;
        rA[j] = e1; rA2[j] = e2;
        s1 += e1; s2 += e2;
    }
#pragma unroll
    for (int o = 16; o; o >>= 1) {
        s1 += __shfl_xor_sync(0xffffffffu, s1, o);
        s2 += __shfl_xor_sync(0xffffffffu, s2, o);
    }
    if (lane == 0) { wr1[w] = s1; wr2[w] = s2; }
    __syncthreads();
    if (w == 0 && lane < 16) {
        s1 = wr1[lane]; s2 = wr2[lane];
#pragma unroll
        for (int o = 8; o; o >>= 1) {
            s1 += __shfl_xor_sync(0xffffu, s1, o);
            s2 += __shfl_xor_sync(0xffffu, s2, o);
        }
        if (lane == 0) { bc1 = s1; bc2 = s2; }
    }
    __syncthreads();
    float inv1 = (bc1 > 0.f) ? 1.f / bc1 : 0.f;
    float inv2 = (bc2 > 0.f) ? 1.f / bc2 : 0.f;

    // combine both softmaxes into ONE weight per column: rA[j] = e1*inv1 + e2*inv2
    for (int q = t; q < L; q += 512) {
        int j = lst[q];
        rA[j] = rA[j] * inv1 + rA2[j] * inv2;
    }
    __syncthreads();

    // weighted accumulation over list; 16 warps x 32 lanes x float2, single weight
    const float2* __restrict__ ue2 = (const float2*)g_ue;
    float2 o1 = make_float2(0.f, 0.f);
    int q = w;
    for (; q + 48 < L; q += 64) {
        int j0 = lst[q], j1 = lst[q + 16], j2 = lst[q + 32], j3 = lst[q + 48];
        float2 u0 = ue2[j0 * 32 + lane];
        float2 u1 = ue2[j1 * 32 + lane];
        float2 u2 = ue2[j2 * 32 + lane];
        float2 u3 = ue2[j3 * 32 + lane];
        float p0 = rA[j0], p1 = rA[j1], p2 = rA[j2], p3 = rA[j3];
        o1.x += p0 * u0.x; o1.y += p0 * u0.y;
        o1.x += p1 * u1.x; o1.y += p1 * u1.y;
        o1.x += p2 * u2.x; o1.y += p2 * u2.y;
        o1.x += p3 * u3.x; o1.y += p3 * u3.y;
    }
    for (; q < L; q += 16) {
        int j = lst[q];
        float2 u = ue2[j * 32 + lane];
        float p = rA[j];
        o1.x += p * u.x; o1.y += p * u.y;
    }
    sg[w][lane] = o1;
    __syncthreads();
    if (t < 32) {
        float tx = 0.f, ty = 0.f;
#pragma unroll
        for (int gg = 0; gg < 16; gg++) { tx += sg[gg][lane].x; ty += sg[gg][lane].y; }
        float2 u = ue2[i * 32 + lane];
        out2[i * 32 + lane] = make_float2(
            (4.f / 3.f) * u.x + tx * (1.f / 3.f),
            (4.f / 3.f) * u.y + ty * (1.f / 3.f));
    }
}

// ---------------- launch ----------------
extern "C" void kernel_launch(void* const* d_in, const int* in_sizes, int n_in,
                              void* d_out, int out_size) {
    const float* ue_in = (const float*)d_in[0];
    const float* ie_in = (const float*)d_in[1];
    const float* ivals = (const float*)d_in[2];
    const float* Wa    = (const float*)d_in[3];
    const float* Wb    = (const float*)d_in[4];
    const float* w1    = (const float*)d_in[5];
    const float* b1    = (const float*)d_in[6];
    const float* w2    = (const float*)d_in[7];
    const float* b2    = (const float*)d_in[8];
    const int* irows   = (const int*)d_in[9];
    const int* icols   = (const int*)d_in[10];
    const int* srows   = (const int*)d_in[11];
    const int* scols   = (const int*)d_in[12];

    k_zero_kab<<<81 + 32, 256>>>(Wa, Wb, w1);
    k_hist_pab<<<1024 + 128 + 256, 256>>>(irows, srows, ue_in, b1);
    k_scan_edge<<<2 + 256, 1024>>>(srows, scols, w2, b2);
    k_scatter_both<<<1024 + 128, 256>>>(irows, icols, ivals, srows, scols);

    k_spmm<1><<<NNODES / 8, dim3(32, 8)>>>((const float2*)ue_in, (const float2*)ie_in);
    k_spmm<2><<<NNODES / 8, dim3(32, 8)>>>((const float2*)ue_in, (const float2*)ie_in);
    k_spmm<3><<<UU / 8,     dim3(32, 8)>>>((const float2*)ue_in, (const float2*)ie_in);

    k_social<<<UU, 512>>>((float2*)d_out);
}

// round 8
// speedup vs baseline: 3.8649x; 1.1065x over previous
#include <cuda_runtime.h>
#include <cuda_fp16.h>
#include <math.h>

#define UU 4096
#define II 16384
#define DD 64
#define NNODES (UU + II)   // 20480
#define NEI 524288
#define NES 65536

// ---------------- device scratch (no allocation allowed) ----------------
__device__ __half2 g_h1h[NNODES * 32];  // layer-1 output (fp16)
__device__ __half2 g_h2h[NNODES * 32];  // layer-2 output (fp16)
__device__ float   g_acc[UU * DD];      // running fp32 sum h0+h1+h2 (user rows)
__device__ float   g_ue[UU * DD];       // final lightgcn user embedding (fp32)
__device__ __half2 g_ue16[UU * 32];     // fp16 mirror for social gather

__device__ int    g_cnt_i[NNODES + 1];
__device__ int    g_rptr_i[NNODES + 1];
__device__ int    g_cur_i[NNODES + 1];
__device__ float2 g_ep[NEI];            // packed (col-as-float-bits, val)

__device__ int    g_cnt_s[UU + 1];
__device__ int    g_rptr_s[UU + 1];
__device__ int    g_cur_s[UU + 1];
__device__ int    g_colp_s[NES];
__device__ float  g_valp_s[NES];
__device__ float  g_ew[NES];            // per-edge sigmoid weight

__device__ float  g_Ka[DD * DD];
__device__ float  g_Kb[DD * DD];
__device__ float  g_Pa[UU * DD];
__device__ float  g_Pb[UU * DD];

// ======================= chain A: interaction graph =======================

__global__ void k_zero_i() {
    int t = blockIdx.x * blockDim.x + threadIdx.x;
    if (t <= NNODES) g_cnt_i[t] = 0;
}

__global__ void k_hist_i(const int* __restrict__ irows) {
    for (int e = blockIdx.x * 256 + threadIdx.x; e < NEI; e += 1024 * 256)
        atomicAdd(&g_cnt_i[irows[e]], 1);
}

template <int NCH>
__device__ void scan_impl(const int* __restrict__ cnt, int* rptr, int* cur, int n) {
    __shared__ int wsum[32];
    __shared__ int tot;
    int t = threadIdx.x, lane = t & 31, w = t >> 5;
    int v[NCH];
#pragma unroll
    for (int c = 0; c < NCH; c++) {
        int i = c * 1024 + t;
        v[c] = (i < n) ? cnt[i] : 0;
    }
    int off = 0;
#pragma unroll
    for (int c = 0; c < NCH; c++) {
        int x = v[c];
#pragma unroll
        for (int d = 1; d < 32; d <<= 1) {
            int y = __shfl_up_sync(0xffffffffu, x, d);
            if (lane >= d) x += y;
        }
        if (lane == 31) wsum[w] = x;
        __syncthreads();
        if (w == 0) {
            int s = wsum[lane];
            int xs = s;
#pragma unroll
            for (int d = 1; d < 32; d <<= 1) {
                int y = __shfl_up_sync(0xffffffffu, xs, d);
                if (lane >= d) xs += y;
            }
            wsum[lane] = xs - s;
            if (lane == 31) tot = xs;
        }
        __syncthreads();
        int excl = off + wsum[w] + x - v[c];
        int i = c * 1024 + t;
        if (i < n) { rptr[i] = excl; cur[i] = excl; }
        off += tot;
        __syncthreads();
    }
    if (t == 0) { rptr[n] = off; cur[n] = off; }
}

__global__ void k_scan_i() {
    scan_impl<NNODES / 1024>(g_cnt_i, g_rptr_i, g_cur_i, NNODES);
}

__global__ void k_scatter_i(const int* __restrict__ irows, const int* __restrict__ icols,
                            const float* __restrict__ ivals) {
    for (int e = blockIdx.x * 256 + threadIdx.x; e < NEI; e += 1024 * 256) {
        int r = irows[e];
        int p = atomicAdd(&g_cur_i[r], 1);
        g_ep[p] = make_float2(__int_as_float(icols[e]), ivals[e]);
    }
}

// SpMM: 32 lanes x 2 dims per row, 8 rows/block
template <int LAYER>
__global__ void k_spmm(const float2* __restrict__ uin2, const float2* __restrict__ iin2) {
    int row = blockIdx.x * 8 + threadIdx.y;
    int lane = threadIdx.x;
    float2* __restrict__ acc2 = (float2*)g_acc;

    int b = g_rptr_i[row], e = g_rptr_i[row + 1];
    float ax = 0.f, ay = 0.f;

    auto fetch = [&](int c) -> float2 {
        if (LAYER == 1) return (c < UU) ? uin2[c * 32 + lane] : iin2[(c - UU) * 32 + lane];
        else if (LAYER == 2) return __half22float2(g_h1h[c * 32 + lane]);
        else return __half22float2(g_h2h[c * 32 + lane]);
    };

    int k = b;
    for (; k + 3 < e; k += 4) {
        float2 e0 = g_ep[k],     e1 = g_ep[k + 1];
        float2 e2 = g_ep[k + 2], e3 = g_ep[k + 3];
        float2 x0 = fetch(__float_as_int(e0.x));
        float2 x1 = fetch(__float_as_int(e1.x));
        float2 x2 = fetch(__float_as_int(e2.x));
        float2 x3 = fetch(__float_as_int(e3.x));
        ax += e0.y * x0.x; ay += e0.y * x0.y;
        ax += e1.y * x1.x; ay += e1.y * x1.y;
        ax += e2.y * x2.x; ay += e2.y * x2.y;
        ax += e3.y * x3.x; ay += e3.y * x3.y;
    }
    for (; k < e; k++) {
        float2 ev = g_ep[k];
        float2 x = fetch(__float_as_int(ev.x));
        ax += ev.y * x.x; ay += ev.y * x.y;
    }

    int o = row * 32 + lane;
    if (LAYER == 1) {
        g_h1h[o] = __floats2half2_rn(ax, ay);
        if (row < UU) {
            float2 u = uin2[o];
            acc2[o] = make_float2(u.x + ax, u.y + ay);
        }
    } else if (LAYER == 2) {
        g_h2h[o] = __floats2half2_rn(ax, ay);
        if (row < UU) {
            float2 a = acc2[o];
            acc2[o] = make_float2(a.x + ax, a.y + ay);
        }
    } else {
        // user rows only (grid = UU/8)
        float2 a = acc2[o];
        float2 u = make_float2((a.x + ax) * 0.25f, (a.y + ay) * 0.25f);
        ((float2*)g_ue)[o] = u;
        g_ue16[o] = __floats2half2_rn(u.x, u.y);
    }
}

// ======================= chain B: social graph =======================

// zero social counters + Ka/Kb GEMM
__global__ void k_zero_s_kab(const float* __restrict__ Wa, const float* __restrict__ Wb,
                             const float* __restrict__ w1) {
    int b = blockIdx.x;
    if (b < 17) {
        int t = b * 256 + threadIdx.x;
        if (t <= UU) g_cnt_s[t] = 0;
    } else {
        int t = (b - 17) * 256 + threadIdx.x;   // 0..8191
        int which = t >> 12;
        int idx = t & 4095;
        int k = idx >> 6, j = idx & 63;
        const float* W = which ? Wb : Wa;
        const float* w1p = which ? (w1 + 64 * 64) : w1;
        float s = 0.f;
#pragma unroll 8
        for (int m = 0; m < 64; m++) s += W[k * 64 + m] * w1p[m * 64 + j];
        if (which) g_Kb[idx] = s; else g_Ka[idx] = s;
    }
}

// social histogram + Pa/Pb GEMM
__global__ void k_hist_s_pab(const int* __restrict__ srows,
                             const float* __restrict__ ue_in, const float* __restrict__ b1) {
    int b = blockIdx.x;
    if (b < 128) {
        for (int e = b * 256 + threadIdx.x; e < NES; e += 128 * 256)
            atomicAdd(&g_cnt_s[srows[e]], 1);
    } else {
        __shared__ float sKa[64 * 64];
        __shared__ float sKb[64 * 64];
        int t = threadIdx.x;
        for (int q = t; q < 4096; q += 256) { sKa[q] = g_Ka[q]; sKb[q] = g_Kb[q]; }
        __syncthreads();
        int j = t & 63;
        int isub = t >> 6;
        int i0 = (b - 128) * 16;
        for (int ii = isub; ii < 16; ii += 4) {
            int i = i0 + ii;
            float a = 0.f, bb = 0.f;
#pragma unroll 8
            for (int k = 0; k < 64; k++) {
                float u = ue_in[i * 64 + k];
                a += u * sKa[k * 64 + j];
                bb += u * sKb[k * 64 + j];
            }
            g_Pa[i * 64 + j] = a;
            g_Pb[i * 64 + j] = bb + b1[j];
        }
    }
}

// social scan + parallel edge MLP (one warp per edge)
__global__ void k_scan_s_edge(const int* __restrict__ srows, const int* __restrict__ scols,
                              const float* __restrict__ w2, const float* __restrict__ b2) {
    int b = blockIdx.x;
    if (b == 0) {
        scan_impl<UU / 1024>(g_cnt_s, g_rptr_s, g_cur_s, UU);
    } else {
        int lane = threadIdx.x & 31;
        int wg = (b - 1) * 32 + (threadIdx.x >> 5);   // 256 blocks * 32 warps = 8192
        const float2* __restrict__ Pa2 = (const float2*)g_Pa;
        const float2* __restrict__ Pb2 = (const float2*)g_Pb;
        float2 wv = ((const float2*)w2)[lane];
        float bias = b2[0];
        for (int e = wg; e < NES; e += 8192) {
            int r = srows[e], c = scols[e];
            float2 pa = Pa2[c * 32 + lane];
            float2 pb = Pb2[r * 32 + lane];
            float h0 = fmaxf(pa.x + pb.x, 0.f);
            float h1 = fmaxf(pa.y + pb.y, 0.f);
            float pv = h0 * wv.x + h1 * wv.y;
#pragma unroll
            for (int o = 16; o; o >>= 1) pv += __shfl_down_sync(0xffffffffu, pv, o);
            if (lane == 0) g_ew[e] = 1.f / (1.f + __expf(-(pv + bias)));
        }
    }
}

__global__ void k_scatter_s(const int* __restrict__ srows, const int* __restrict__ scols) {
    for (int e = blockIdx.x * 256 + threadIdx.x; e < NES; e += 128 * 256) {
        int r = srows[e];
        int p = atomicAdd(&g_cur_s[r], 1);
        g_colp_s[p] = scols[e];
        g_valp_s[p] = g_ew[e];
    }
}

// ======================= join: social propagation =======================

__global__ void __launch_bounds__(512) k_social(float2* __restrict__ out2) {
    __shared__ float rA[UU];             // 16 KB
    __shared__ float rA2[UU];            // 16 KB
    __shared__ unsigned short lst[UU];   // 8 KB
    __shared__ int nlst;
    __shared__ float wr1[16], wr2[16];
    __shared__ float bc1, bc2;
    __shared__ float2 sg[16][32];        // 4 KB

    int i = blockIdx.x;
    int t = threadIdx.x;   // 512
    int lane = t & 31, w = t >> 5;

    float4* rA4 = (float4*)rA;
    float4* rB4 = (float4*)rA2;
    float4 z4 = make_float4(0.f, 0.f, 0.f, 0.f);
#pragma unroll
    for (int q = t; q < UU / 4; q += 512) { rA4[q] = z4; rB4[q] = z4; }
    if (t == 0) nlst = 0;
    __syncthreads();

    int b = g_rptr_s[i], e = g_rptr_s[i + 1];
    // depth-1 merged row
    for (int k = b + t; k < e; k += 512)
        atomicAdd(&rA[g_colp_s[k]], g_valp_s[k]);
    // depth-2: 16 threads per neighbor
    for (int k = b + (t >> 4); k < e; k += 32) {
        int kk = g_colp_s[k];
        float wv = g_valp_s[k];
        int b2i = g_rptr_s[kk], e2i = g_rptr_s[kk + 1];
        for (int m = b2i + (t & 15); m < e2i; m += 16)
            atomicAdd(&rA2[g_colp_s[m]], wv * g_valp_s[m]);
    }
    __syncthreads();

    // compaction fused with max computation
    float m1 = -1e30f, m2 = -1e30f;
#pragma unroll
    for (int j = t; j < UU; j += 512) {
        float a1 = rA[j], a2 = rA2[j];
        bool nz = (a1 > 0.f) || (a2 > 0.f);
        m1 = fmaxf(m1, a1 > 0.f ? a1 : -1e30f);
        m2 = fmaxf(m2, a2 > 0.f ? a2 : -1e30f);
        unsigned mask = __ballot_sync(0xffffffffu, nz);
        if (nz) {
            int lead = __ffs(mask) - 1;
            int basep = 0;
            if (lane == lead) basep = atomicAdd(&nlst, __popc(mask));
            basep = __shfl_sync(mask, basep, lead);
            int off = __popc(mask & ((1u << lane) - 1u));
            lst[basep + off] = (unsigned short)j;
        }
    }
#pragma unroll
    for (int o = 16; o; o >>= 1) {
        m1 = fmaxf(m1, __shfl_xor_sync(0xffffffffu, m1, o));
        m2 = fmaxf(m2, __shfl_xor_sync(0xffffffffu, m2, o));
    }
    if (lane == 0) { wr1[w] = m1; wr2[w] = m2; }
    __syncthreads();
    if (w == 0 && lane < 16) {
        m1 = wr1[lane]; m2 = wr2[lane];
#pragma unroll
        for (int o = 8; o; o >>= 1) {
            m1 = fmaxf(m1, __shfl_xor_sync(0xffffu, m1, o));
            m2 = fmaxf(m2, __shfl_xor_sync(0xffffu, m2, o));
        }
        if (lane == 0) { bc1 = m1; bc2 = m2; }
    }
    __syncthreads();
    m1 = bc1; m2 = bc2;
    int L = nlst;
    __syncthreads();

    // exp + sums (writeback; list entries unique)
    float s1 = 0.f, s2 = 0.f;
    for (int q = t; q < L; q += 512) {
        int j = lst[q];
        float a1 = rA[j], a2 = rA2[j];
        float e1 = (a1 > 0.f) ? __expf(a1 - m1) : 0.f;
        float e2 = (a2 > 0.f) ? __expf(a2 - m2) : 0.f;
        rA[j] = e1; rA2[j] = e2;
        s1 += e1; s2 += e2;
    }
#pragma unroll
    for (int o = 16; o; o >>= 1) {
        s1 += __shfl_xor_sync(0xffffffffu, s1, o);
        s2 += __shfl_xor_sync(0xffffffffu, s2, o);
    }
    if (lane == 0) { wr1[w] = s1; wr2[w] = s2; }
    __syncthreads();
    if (w == 0 && lane < 16) {
        s1 = wr1[lane]; s2 = wr2[lane];
#pragma unroll
        for (int o = 8; o; o >>= 1) {
            s1 += __shfl_xor_sync(0xffffu, s1, o);
            s2 += __shfl_xor_sync(0xffffu, s2, o);
        }
        if (lane == 0) { bc1 = s1; bc2 = s2; }
    }
    __syncthreads();
    float inv1 = (bc1 > 0.f) ? 1.f / bc1 : 0.f;
    float inv2 = (bc2 > 0.f) ? 1.f / bc2 : 0.f;

    // combine both softmaxes into ONE weight per column
    for (int q = t; q < L; q += 512) {
        int j = lst[q];
        rA[j] = rA[j] * inv1 + rA2[j] * inv2;
    }
    __syncthreads();

    // weighted accumulation over list from fp16 ue; 16 warps x 32 lanes
    float2 o1 = make_float2(0.f, 0.f);
    int q = w;
    for (; q + 48 < L; q += 64) {
        int j0 = lst[q], j1 = lst[q + 16], j2 = lst[q + 32], j3 = lst[q + 48];
        float2 u0 = __half22float2(g_ue16[j0 * 32 + lane]);
        float2 u1 = __half22float2(g_ue16[j1 * 32 + lane]);
        float2 u2 = __half22float2(g_ue16[j2 * 32 + lane]);
        float2 u3 = __half22float2(g_ue16[j3 * 32 + lane]);
        float p0 = rA[j0], p1 = rA[j1], p2 = rA[j2], p3 = rA[j3];
        o1.x += p0 * u0.x; o1.y += p0 * u0.y;
        o1.x += p1 * u1.x; o1.y += p1 * u1.y;
        o1.x += p2 * u2.x; o1.y += p2 * u2.y;
        o1.x += p3 * u3.x; o1.y += p3 * u3.y;
    }
    for (; q < L; q += 16) {
        int j = lst[q];
        float2 u = __half22float2(g_ue16[j * 32 + lane]);
        float p = rA[j];
        o1.x += p * u.x; o1.y += p * u.y;
    }
    sg[w][lane] = o1;
    __syncthreads();
    if (t < 32) {
        float tx = 0.f, ty = 0.f;
#pragma unroll
        for (int gg = 0; gg < 16; gg++) { tx += sg[gg][lane].x; ty += sg[gg][lane].y; }
        float2 u = ((const float2*)g_ue)[i * 32 + lane];
        out2[i * 32 + lane] = make_float2(
            (4.f / 3.f) * u.x + tx * (1.f / 3.f),
            (4.f / 3.f) * u.y + ty * (1.f / 3.f));
    }
}

// ---------------- launch: two-stream fork/join DAG ----------------
extern "C" void kernel_launch(void* const* d_in, const int* in_sizes, int n_in,
                              void* d_out, int out_size) {
    const float* ue_in = (const float*)d_in[0];
    const float* ie_in = (const float*)d_in[1];
    const float* ivals = (const float*)d_in[2];
    const float* Wa    = (const float*)d_in[3];
    const float* Wb    = (const float*)d_in[4];
    const float* w1    = (const float*)d_in[5];
    const float* b1    = (const float*)d_in[6];
    const float* w2    = (const float*)d_in[7];
    const float* b2    = (const float*)d_in[8];
    const int* irows   = (const int*)d_in[9];
    const int* icols   = (const int*)d_in[10];
    const int* srows   = (const int*)d_in[11];
    const int* scols   = (const int*)d_in[12];

    static cudaStream_t sB = nullptr;
    static cudaEvent_t evFork = nullptr, evJoin = nullptr;
    if (sB == nullptr) {
        cudaStreamCreateWithFlags(&sB, cudaStreamNonBlocking);
        cudaEventCreateWithFlags(&evFork, cudaEventDisableTiming);
        cudaEventCreateWithFlags(&evJoin, cudaEventDisableTiming);
    }

    // fork
    cudaEventRecord(evFork, 0);
    cudaStreamWaitEvent(sB, evFork, 0);

    // chain B (social CSR + edge MLP) on sB
    k_zero_s_kab<<<17 + 32, 256, 0, sB>>>(Wa, Wb, w1);
    k_hist_s_pab<<<128 + 256, 256, 0, sB>>>(srows, ue_in, b1);
    k_scan_s_edge<<<1 + 256, 1024, 0, sB>>>(srows, scols, w2, b2);
    k_scatter_s<<<128, 256, 0, sB>>>(srows, scols);
    cudaEventRecord(evJoin, sB);

    // chain A (interaction CSR + LightGCN) on main stream
    k_zero_i<<<81, 256>>>();
    k_hist_i<<<1024, 256>>>(irows);
    k_scan_i<<<1, 1024>>>();
    k_scatter_i<<<1024, 256>>>(irows, icols, ivals);
    k_spmm<1><<<NNODES / 8, dim3(32, 8)>>>((const float2*)ue_in, (const float2*)ie_in);
    k_spmm<2><<<NNODES / 8, dim3(32, 8)>>>((const float2*)ue_in, (const float2*)ie_in);
    k_spmm<3><<<UU / 8,     dim3(32, 8)>>>((const float2*)ue_in, (const float2*)ie_in);

    // join, then social propagation
    cudaStreamWaitEvent(0, evJoin, 0);
    k_social<<<UU, 512>>>((float2*)d_out);
}

// round 9
// speedup vs baseline: 4.1545x; 1.0749x over previous
#include <cuda_runtime.h>
#include <cuda_fp16.h>
#include <math.h>

#define UU 4096
#define II 16384
#define DD 64
#define NNODES (UU + II)   // 20480
#define NEI 524288
#define NES 65536

// ---------------- device scratch (no allocation allowed) ----------------
__device__ __half2 g_e16[NNODES * 32];  // fp16 copy of [user_emb; item_emb]
__device__ __half2 g_h1h[NNODES * 32];  // layer-1 output (fp16)
__device__ __half2 g_h2h[NNODES * 32];  // layer-2 output (fp16)
__device__ float   g_acc[UU * DD];      // running fp32 sum h0+h1+h2 (user rows)
__device__ float   g_ue[UU * DD];       // final lightgcn user embedding (fp32)
__device__ __half2 g_ue16[UU * 32];     // fp16 mirror for social gather

__device__ int    g_cnt_i[NNODES + 1];
__device__ int    g_rptr_i[NNODES + 1];
__device__ int    g_cur_i[NNODES + 1];
__device__ float2 g_ep[NEI];            // packed (col-as-float-bits, val)

__device__ int    g_cnt_s[UU + 1];
__device__ int    g_rptr_s[UU + 1];
__device__ int    g_cur_s[UU + 1];
__device__ int    g_colp_s[NES];
__device__ float  g_valp_s[NES];
__device__ float  g_ew[NES];            // per-edge sigmoid weight

__device__ float  g_Ka[DD * DD];
__device__ float  g_Kb[DD * DD];
__device__ float  g_Pa[UU * DD];
__device__ float  g_Pb[UU * DD];

// ======================= chain C: input fp16 conversion =======================
__global__ void k_cvt(const float2* __restrict__ uin2, const float2* __restrict__ iin2) {
    int t = blockIdx.x * blockDim.x + threadIdx.x;   // NNODES*32 half2 elems
    if (t < UU * 32) {
        float2 v = uin2[t];
        g_e16[t] = __floats2half2_rn(v.x, v.y);
    } else if (t < NNODES * 32) {
        float2 v = iin2[t - UU * 32];
        g_e16[t] = __floats2half2_rn(v.x, v.y);
    }
}

// ======================= chain A: interaction graph =======================

__global__ void k_zero_i() {
    int t = blockIdx.x * blockDim.x + threadIdx.x;
    if (t <= NNODES) g_cnt_i[t] = 0;
}

__global__ void k_hist_i(const int* __restrict__ irows) {
    for (int e = blockIdx.x * 256 + threadIdx.x; e < NEI; e += 1024 * 256)
        atomicAdd(&g_cnt_i[irows[e]], 1);
}

template <int NCH>
__device__ void scan_impl(const int* __restrict__ cnt, int* rptr, int* cur, int n) {
    __shared__ int wsum[32];
    __shared__ int tot;
    int t = threadIdx.x, lane = t & 31, w = t >> 5;
    int v[NCH];
#pragma unroll
    for (int c = 0; c < NCH; c++) {
        int i = c * 1024 + t;
        v[c] = (i < n) ? cnt[i] : 0;
    }
    int off = 0;
#pragma unroll
    for (int c = 0; c < NCH; c++) {
        int x = v[c];
#pragma unroll
        for (int d = 1; d < 32; d <<= 1) {
            int y = __shfl_up_sync(0xffffffffu, x, d);
            if (lane >= d) x += y;
        }
        if (lane == 31) wsum[w] = x;
        __syncthreads();
        if (w == 0) {
            int s = wsum[lane];
            int xs = s;
#pragma unroll
            for (int d = 1; d < 32; d <<= 1) {
                int y = __shfl_up_sync(0xffffffffu, xs, d);
                if (lane >= d) xs += y;
            }
            wsum[lane] = xs - s;
            if (lane == 31) tot = xs;
        }
        __syncthreads();
        int excl = off + wsum[w] + x - v[c];
        int i = c * 1024 + t;
        if (i < n) { rptr[i] = excl; cur[i] = excl; }
        off += tot;
        __syncthreads();
    }
    if (t == 0) { rptr[n] = off; cur[n] = off; }
}

__global__ void k_scan_i() {
    scan_impl<NNODES / 1024>(g_cnt_i, g_rptr_i, g_cur_i, NNODES);
}

__global__ void k_scatter_i(const int* __restrict__ irows, const int* __restrict__ icols,
                            const float* __restrict__ ivals) {
    int e = blockIdx.x * 256 + threadIdx.x;   // 2048 blocks: one edge per thread
    if (e < NEI) {
        int r = irows[e];
        int p = atomicAdd(&g_cur_i[r], 1);
        g_ep[p] = make_float2(__int_as_float(icols[e]), ivals[e]);
    }
}

// SpMM: 32 lanes x 2 dims per row, 8 rows/block
template <int LAYER>
__global__ void k_spmm(const float2* __restrict__ uin2) {
    int row = blockIdx.x * 8 + threadIdx.y;
    int lane = threadIdx.x;
    float2* __restrict__ acc2 = (float2*)g_acc;

    int b = g_rptr_i[row], e = g_rptr_i[row + 1];
    float ax = 0.f, ay = 0.f;

    auto fetch = [&](int c) -> float2 {
        if (LAYER == 1) return __half22float2(g_e16[c * 32 + lane]);
        else if (LAYER == 2) return __half22float2(g_h1h[c * 32 + lane]);
        else return __half22float2(g_h2h[c * 32 + lane]);
    };

    int k = b;
    for (; k + 3 < e; k += 4) {
        float2 e0 = g_ep[k],     e1 = g_ep[k + 1];
        float2 e2 = g_ep[k + 2], e3 = g_ep[k + 3];
        float2 x0 = fetch(__float_as_int(e0.x));
        float2 x1 = fetch(__float_as_int(e1.x));
        float2 x2 = fetch(__float_as_int(e2.x));
        float2 x3 = fetch(__float_as_int(e3.x));
        ax += e0.y * x0.x; ay += e0.y * x0.y;
        ax += e1.y * x1.x; ay += e1.y * x1.y;
        ax += e2.y * x2.x; ay += e2.y * x2.y;
        ax += e3.y * x3.x; ay += e3.y * x3.y;
    }
    for (; k < e; k++) {
        float2 ev = g_ep[k];
        float2 x = fetch(__float_as_int(ev.x));
        ax += ev.y * x.x; ay += ev.y * x.y;
    }

    int o = row * 32 + lane;
    if (LAYER == 1) {
        g_h1h[o] = __floats2half2_rn(ax, ay);
        if (row < UU) {
            float2 u = uin2[o];
            acc2[o] = make_float2(u.x + ax, u.y + ay);
        }
    } else if (LAYER == 2) {
        g_h2h[o] = __floats2half2_rn(ax, ay);
        if (row < UU) {
            float2 a = acc2[o];
            acc2[o] = make_float2(a.x + ax, a.y + ay);
        }
    } else {
        // user rows only (grid = UU/8)
        float2 a = acc2[o];
        float2 u = make_float2((a.x + ax) * 0.25f, (a.y + ay) * 0.25f);
        ((float2*)g_ue)[o] = u;
        g_ue16[o] = __floats2half2_rn(u.x, u.y);
    }
}

// ======================= chain B: social graph =======================

__global__ void k_zero_s_kab(const float* __restrict__ Wa, const float* __restrict__ Wb,
                             const float* __restrict__ w1) {
    int b = blockIdx.x;
    if (b < 17) {
        int t = b * 256 + threadIdx.x;
        if (t <= UU) g_cnt_s[t] = 0;
    } else {
        int t = (b - 17) * 256 + threadIdx.x;   // 0..8191
        int which = t >> 12;
        int idx = t & 4095;
        int k = idx >> 6, j = idx & 63;
        const float* W = which ? Wb : Wa;
        const float* w1p = which ? (w1 + 64 * 64) : w1;
        float s = 0.f;
#pragma unroll 8
        for (int m = 0; m < 64; m++) s += W[k * 64 + m] * w1p[m * 64 + j];
        if (which) g_Kb[idx] = s; else g_Ka[idx] = s;
    }
}

__global__ void k_hist_s_pab(const int* __restrict__ srows,
                             const float* __restrict__ ue_in, const float* __restrict__ b1) {
    int b = blockIdx.x;
    if (b < 128) {
        for (int e = b * 256 + threadIdx.x; e < NES; e += 128 * 256)
            atomicAdd(&g_cnt_s[srows[e]], 1);
    } else {
        __shared__ float sKa[64 * 64];
        __shared__ float sKb[64 * 64];
        int t = threadIdx.x;
        for (int q = t; q < 4096; q += 256) { sKa[q] = g_Ka[q]; sKb[q] = g_Kb[q]; }
        __syncthreads();
        int j = t & 63;
        int isub = t >> 6;
        int i0 = (b - 128) * 16;
        for (int ii = isub; ii < 16; ii += 4) {
            int i = i0 + ii;
            float a = 0.f, bb = 0.f;
#pragma unroll 8
            for (int k = 0; k < 64; k++) {
                float u = ue_in[i * 64 + k];
                a += u * sKa[k * 64 + j];
                bb += u * sKb[k * 64 + j];
            }
            g_Pa[i * 64 + j] = a;
            g_Pb[i * 64 + j] = bb + b1[j];
        }
    }
}

__global__ void k_scan_s_edge(const int* __restrict__ srows, const int* __restrict__ scols,
                              const float* __restrict__ w2, const float* __restrict__ b2) {
    int b = blockIdx.x;
    if (b == 0) {
        scan_impl<UU / 1024>(g_cnt_s, g_rptr_s, g_cur_s, UU);
    } else {
        int lane = threadIdx.x & 31;
        int wg = (b - 1) * 32 + (threadIdx.x >> 5);   // 256 blocks * 32 warps = 8192
        const float2* __restrict__ Pa2 = (const float2*)g_Pa;
        const float2* __restrict__ Pb2 = (const float2*)g_Pb;
        float2 wv = ((const float2*)w2)[lane];
        float bias = b2[0];
        for (int e = wg; e < NES; e += 8192) {
            int r = srows[e], c = scols[e];
            float2 pa = Pa2[c * 32 + lane];
            float2 pb = Pb2[r * 32 + lane];
            float h0 = fmaxf(pa.x + pb.x, 0.f);
            float h1 = fmaxf(pa.y + pb.y, 0.f);
            float pv = h0 * wv.x + h1 * wv.y;
#pragma unroll
            for (int o = 16; o; o >>= 1) pv += __shfl_down_sync(0xffffffffu, pv, o);
            if (lane == 0) g_ew[e] = 1.f / (1.f + __expf(-(pv + bias)));
        }
    }
}

__global__ void k_scatter_s(const int* __restrict__ srows, const int* __restrict__ scols) {
    int e = blockIdx.x * 256 + threadIdx.x;   // 256 blocks: one edge per thread
    if (e < NES) {
        int r = srows[e];
        int p = atomicAdd(&g_cur_s[r], 1);
        g_colp_s[p] = scols[e];
        g_valp_s[p] = g_ew[e];
    }
}

// ======================= join: social propagation =======================

__global__ void __launch_bounds__(512) k_social(float2* __restrict__ out2) {
    __shared__ float rA[UU];             // 16 KB
    __shared__ float rA2[UU];            // 16 KB
    __shared__ unsigned short lst[UU];   // 8 KB
    __shared__ int nlst;
    __shared__ float wr1[16], wr2[16];
    __shared__ float bc1, bc2;
    __shared__ float2 sg[16][32];        // 4 KB

    int i = blockIdx.x;
    int t = threadIdx.x;   // 512
    int lane = t & 31, w = t >> 5;

    float4* rA4 = (float4*)rA;
    float4* rB4 = (float4*)rA2;
    float4 z4 = make_float4(0.f, 0.f, 0.f, 0.f);
#pragma unroll
    for (int q = t; q < UU / 4; q += 512) { rA4[q] = z4; rB4[q] = z4; }
    if (t == 0) nlst = 0;
    __syncthreads();

    int b = g_rptr_s[i], e = g_rptr_s[i + 1];
    for (int k = b + t; k < e; k += 512)
        atomicAdd(&rA[g_colp_s[k]], g_valp_s[k]);
    for (int k = b + (t >> 4); k < e; k += 32) {
        int kk = g_colp_s[k];
        float wv = g_valp_s[k];
        int b2i = g_rptr_s[kk], e2i = g_rptr_s[kk + 1];
        for (int m = b2i + (t & 15); m < e2i; m += 16)
            atomicAdd(&rA2[g_colp_s[m]], wv * g_valp_s[m]);
    }
    __syncthreads();

    // compaction fused with max computation
    float m1 = -1e30f, m2 = -1e30f;
#pragma unroll
    for (int j = t; j < UU; j += 512) {
        float a1 = rA[j], a2 = rA2[j];
        bool nz = (a1 > 0.f) || (a2 > 0.f);
        m1 = fmaxf(m1, a1 > 0.f ? a1 : -1e30f);
        m2 = fmaxf(m2, a2 > 0.f ? a2 : -1e30f);
        unsigned mask = __ballot_sync(0xffffffffu, nz);
        if (nz) {
            int lead = __ffs(mask) - 1;
            int basep = 0;
            if (lane == lead) basep = atomicAdd(&nlst, __popc(mask));
            basep = __shfl_sync(mask, basep, lead);
            int off = __popc(mask & ((1u << lane) - 1u));
            lst[basep + off] = (unsigned short)j;
        }
    }
#pragma unroll
    for (int o = 16; o; o >>= 1) {
        m1 = fmaxf(m1, __shfl_xor_sync(0xffffffffu, m1, o));
        m2 = fmaxf(m2, __shfl_xor_sync(0xffffffffu, m2, o));
    }
    if (lane == 0) { wr1[w] = m1; wr2[w] = m2; }
    __syncthreads();
    if (w == 0 && lane < 16) {
        m1 = wr1[lane]; m2 = wr2[lane];
#pragma unroll
        for (int o = 8; o; o >>= 1) {
            m1 = fmaxf(m1, __shfl_xor_sync(0xffffu, m1, o));
            m2 = fmaxf(m2, __shfl_xor_sync(0xffffu, m2, o));
        }
        if (lane == 0) { bc1 = m1; bc2 = m2; }
    }
    __syncthreads();
    m1 = bc1; m2 = bc2;
    int L = nlst;
    __syncthreads();

    // exp + sums (writeback; list entries unique)
    float s1 = 0.f, s2 = 0.f;
    for (int q = t; q < L; q += 512) {
        int j = lst[q];
        float a1 = rA[j], a2 = rA2[j];
        float e1 = (a1 > 0.f) ? __expf(a1 - m1) : 0.f;
        float e2 = (a2 > 0.f) ? __expf(a2 - m2) : 0.f;
        rA[j] = e1; rA2[j] = e2;
        s1 += e1; s2 += e2;
    }
#pragma unroll
    for (int o = 16; o; o >>= 1) {
        s1 += __shfl_xor_sync(0xffffffffu, s1, o);
        s2 += __shfl_xor_sync(0xffffffffu, s2, o);
    }
    if (lane == 0) { wr1[w] = s1; wr2[w] = s2; }
    __syncthreads();
    if (w == 0 && lane < 16) {
        s1 = wr1[lane]; s2 = wr2[lane];
#pragma unroll
        for (int o = 8; o; o >>= 1) {
            s1 += __shfl_xor_sync(0xffffu, s1, o);
            s2 += __shfl_xor_sync(0xffffu, s2, o);
        }
        if (lane == 0) { bc1 = s1; bc2 = s2; }
    }
    __syncthreads();
    float inv1 = (bc1 > 0.f) ? 1.f / bc1 : 0.f;
    float inv2 = (bc2 > 0.f) ? 1.f / bc2 : 0.f;

    // combine both softmaxes into ONE weight per column
    for (int q = t; q < L; q += 512) {
        int j = lst[q];
        rA[j] = rA[j] * inv1 + rA2[j] * inv2;
    }
    __syncthreads();

    // weighted accumulation over list from fp16 ue; 16 warps x 32 lanes
    float2 o1 = make_float2(0.f, 0.f);
    int q = w;
    for (; q + 48 < L; q += 64) {
        int j0 = lst[q], j1 = lst[q + 16], j2 = lst[q + 32], j3 = lst[q + 48];
        float2 u0 = __half22float2(g_ue16[j0 * 32 + lane]);
        float2 u1 = __half22float2(g_ue16[j1 * 32 + lane]);
        float2 u2 = __half22float2(g_ue16[j2 * 32 + lane]);
        float2 u3 = __half22float2(g_ue16[j3 * 32 + lane]);
        float p0 = rA[j0], p1 = rA[j1], p2 = rA[j2], p3 = rA[j3];
        o1.x += p0 * u0.x; o1.y += p0 * u0.y;
        o1.x += p1 * u1.x; o1.y += p1 * u1.y;
        o1.x += p2 * u2.x; o1.y += p2 * u2.y;
        o1.x += p3 * u3.x; o1.y += p3 * u3.y;
    }
    for (; q < L; q += 16) {
        int j = lst[q];
        float2 u = __half22float2(g_ue16[j * 32 + lane]);
        float p = rA[j];
        o1.x += p * u.x; o1.y += p * u.y;
    }
    sg[w][lane] = o1;
    __syncthreads();
    if (t < 32) {
        float tx = 0.f, ty = 0.f;
#pragma unroll
        for (int gg = 0; gg < 16; gg++) { tx += sg[gg][lane].x; ty += sg[gg][lane].y; }
        float2 u = ((const float2*)g_ue)[i * 32 + lane];
        out2[i * 32 + lane] = make_float2(
            (4.f / 3.f) * u.x + tx * (1.f / 3.f),
            (4.f / 3.f) * u.y + ty * (1.f / 3.f));
    }
}

// ---------------- launch: three-stream fork/join DAG ----------------
extern "C" void kernel_launch(void* const* d_in, const int* in_sizes, int n_in,
                              void* d_out, int out_size) {
    const float* ue_in = (const float*)d_in[0];
    const float* ie_in = (const float*)d_in[1];
    const float* ivals = (const float*)d_in[2];
    const float* Wa    = (const float*)d_in[3];
    const float* Wb    = (const float*)d_in[4];
    const float* w1    = (const float*)d_in[5];
    const float* b1    = (const float*)d_in[6];
    const float* w2    = (const float*)d_in[7];
    const float* b2    = (const float*)d_in[8];
    const int* irows   = (const int*)d_in[9];
    const int* icols   = (const int*)d_in[10];
    const int* srows   = (const int*)d_in[11];
    const int* scols   = (const int*)d_in[12];

    static cudaStream_t sB = nullptr, sC = nullptr;
    static cudaEvent_t evFork = nullptr, evJoinB = nullptr, evJoinC = nullptr;
    if (sB == nullptr) {
        cudaStreamCreateWithFlags(&sB, cudaStreamNonBlocking);
        cudaStreamCreateWithFlags(&sC, cudaStreamNonBlocking);
        cudaEventCreateWithFlags(&evFork, cudaEventDisableTiming);
        cudaEventCreateWithFlags(&evJoinB, cudaEventDisableTiming);
        cudaEventCreateWithFlags(&evJoinC, cudaEventDisableTiming);
    }

    // fork
    cudaEventRecord(evFork, 0);
    cudaStreamWaitEvent(sB, evFork, 0);
    cudaStreamWaitEvent(sC, evFork, 0);

    // chain C: fp16 conversion of inputs (hidden under CSR build)
    k_cvt<<<(NNODES * 32 + 255) / 256, 256, 0, sC>>>((const float2*)ue_in, (const float2*)ie_in);
    cudaEventRecord(evJoinC, sC);

    // chain B (social CSR + edge MLP) on sB
    k_zero_s_kab<<<17 + 32, 256, 0, sB>>>(Wa, Wb, w1);
    k_hist_s_pab<<<128 + 256, 256, 0, sB>>>(srows, ue_in, b1);
    k_scan_s_edge<<<1 + 256, 1024, 0, sB>>>(srows, scols, w2, b2);
    k_scatter_s<<<256, 256, 0, sB>>>(srows, scols);
    cudaEventRecord(evJoinB, sB);

    // chain A (interaction CSR + LightGCN) on main stream
    k_zero_i<<<81, 256>>>();
    k_hist_i<<<1024, 256>>>(irows);
    k_scan_i<<<1, 1024>>>();
    k_scatter_i<<<2048, 256>>>(irows, icols, ivals);
    cudaStreamWaitEvent(0, evJoinC, 0);
    k_spmm<1><<<NNODES / 8, dim3(32, 8)>>>((const float2*)ue_in);
    k_spmm<2><<<NNODES / 8, dim3(32, 8)>>>((const float2*)ue_in);
    k_spmm<3><<<UU / 8,     dim3(32, 8)>>>((const float2*)ue_in);

    // join, then social propagation
    cudaStreamWaitEvent(0, evJoinB, 0);
    k_social<<<UU, 512>>>((float2*)d_out);
}